// round 1
// baseline (speedup 1.0000x reference)
#include <cuda_runtime.h>
#include <cuda_bf16.h>
#include <math.h>

#define NN 100000
#define RR 3
#define EE 320000
#define HH 4
#define DD 32
#define HD 128   // H*D
#define HID 128

// ---------------- device scratch (no allocs allowed) ----------------
__device__ __align__(16) float g_hs  [RR * NN * HD];   // per-relation projected src features
__device__ __align__(16) float g_rst [RR * NN * HD];   // aggregation accumulator / z_r
__device__ __align__(16) float g_el  [RR * NN * HH];
__device__ __align__(16) float g_er  [RR * NN * HH];
__device__ __align__(16) float g_m   [RR * NN * HH];
__device__ __align__(16) float g_ssum[RR * NN * HH];
__device__ __align__(16) float g_e   [RR * EE * HH];   // edge scores then exp values
__device__ __align__(16) float g_Wc  [RR * HID * HD];  // fused src weight
__device__ __align__(16) float g_bc  [RR * HD];        // fused src bias
__device__ __align__(16) float g_gvec[RR * HID * HH];  // Wg contracted with attn_r
__device__ __align__(16) float g_url [RR * HH * HID];  // er projection vectors
__device__ __align__(16) float g_erc [RR * HH];        // er consts
__device__ float g_wsum[RR];
__device__ float g_a[RR];

// ---------------- helpers ----------------
__device__ __forceinline__ float lrelu(float x) { return x > 0.f ? x : 0.2f * x; }
__device__ __forceinline__ float elu(float x)   { return x > 0.f ? x : expm1f(x); }

__device__ __forceinline__ void atomicMaxF(float* addr, float v) {
    if (v >= 0.f) atomicMax((int*)addr, __float_as_int(v));
    else          atomicMin((unsigned int*)addr, __float_as_uint(v));
}

// ---------------- init ----------------
__global__ void init_kernel() {
    int g = blockIdx.x * blockDim.x + threadIdx.x;
    int stride = gridDim.x * blockDim.x;
    for (int i = g; i < RR * NN * HD; i += stride) g_rst[i] = 0.f;
    for (int i = g; i < RR * NN * HH; i += stride) { g_m[i] = -INFINITY; g_ssum[i] = 0.f; }
    if (g < RR) g_wsum[g] = 0.f;
}

// ---------------- weight prep ----------------
// gvec[r][t][h] = sum_d Wg[r][t][h*32+d] * attn_r[r][h][d]
// bc[r][j]      = sum_t bt_src[r][t] * Wg[r][t][j]
__global__ void prep1(const float* __restrict__ Wg, const float* __restrict__ attn_r,
                      const float* __restrict__ bt_src) {
    int r = blockIdx.x;
    int t = threadIdx.x;
    const float* wgr = Wg + (size_t)r * HID * HD;
    #pragma unroll
    for (int h = 0; h < HH; h++) {
        float s = 0.f;
        #pragma unroll
        for (int d = 0; d < DD; d++)
            s += wgr[t * HD + h * DD + d] * attn_r[(r * HH + h) * DD + d];
        g_gvec[(r * HID + t) * HH + h] = s;
    }
    float s = 0.f;
    for (int tt = 0; tt < HID; tt++) s += bt_src[r * HID + tt] * wgr[tt * HD + t];
    g_bc[r * HD + t] = s;
}

// Wc[r][k][j] = sum_t Wt_src[r][k][t] * Wg[r][t][j]
// url[r][h][t] = sum_t' Wt_dst[t][t'] * gvec[r][t'][h]
// erc[r][h]   = sum_t' bt_dst[t'] * gvec[r][t'][h]
__global__ void prep2(const float* __restrict__ Wt_src, const float* __restrict__ Wg,
                      const float* __restrict__ Wt_dst, const float* __restrict__ bt_dst) {
    int k = blockIdx.x;
    int r = blockIdx.y;
    int j = threadIdx.x;
    if (k < HID) {
        __shared__ float arow[HID];
        arow[j] = Wt_src[((size_t)r * HID + k) * HID + j];
        __syncthreads();
        float s = 0.f;
        const float* wgr = Wg + (size_t)r * HID * HD;
        for (int t = 0; t < HID; t++) s += arow[t] * wgr[t * HD + j];
        g_Wc[((size_t)r * HID + k) * HD + j] = s;
    } else {
        int t = j;
        #pragma unroll
        for (int h = 0; h < HH; h++) {
            float s = 0.f;
            for (int tp = 0; tp < HID; tp++)
                s += Wt_dst[t * HID + tp] * g_gvec[(r * HID + tp) * HH + h];
            g_url[(r * HH + h) * HID + t] = s;
        }
        if (t < HH) {
            int h = t;
            float s = 0.f;
            for (int tp = 0; tp < HID; tp++)
                s += bt_dst[tp] * g_gvec[(r * HID + tp) * HH + h];
            g_erc[r * HH + h] = s;
        }
    }
}

// ---------------- big GEMM: 128x128 tile, 8x8 per thread, K=128 in chunks of 32 ----------
// MODE 0: C = A@W + bias        (A = src_feats relation slice, W = g_Wc[r], C = g_hs[r])
// MODE 1: semantic attention:   A-load applies elu(x + prebias), epilogue computes
//         sum_j tanh(acc+b1[j])*W2[j] per row, block-reduced into g_wsum[r]
template <int MODE>
__global__ __launch_bounds__(256, 2)
void gemm128_kernel(const float* __restrict__ Abase,
                    const float* __restrict__ Wext,   // MODE1: W1
                    const float* __restrict__ b1,     // MODE1
                    const float* __restrict__ prebias,// MODE1: bias_g base
                    const float* __restrict__ W2,     // MODE1
                    int M) {
    __shared__ __align__(16) float As[128 * 36];
    __shared__ __align__(16) float Ws[32 * 132];
    __shared__ float wrow[128];

    int r = blockIdx.y;
    const float* A;
    const float* W;
    const float* pb = nullptr;
    if (MODE == 0) {
        A = Abase + (size_t)r * NN * HID;
        W = g_Wc + (size_t)r * HID * HD;
    } else {
        A = g_rst + (size_t)r * NN * HD;
        W = Wext;
        pb = prebias + r * HD;
    }

    int tid = threadIdx.x;
    int tx = tid & 15, ty = tid >> 4;
    int row0 = blockIdx.x * 128;

    float acc[8][8];
    #pragma unroll
    for (int i = 0; i < 8; i++)
        #pragma unroll
        for (int j = 0; j < 8; j++) acc[i][j] = 0.f;

    for (int k0 = 0; k0 < 128; k0 += 32) {
        // stage A tile (128 rows x 32 cols), pad 36
        #pragma unroll
        for (int u = 0; u < 4; u++) {
            int f4 = u * 256 + tid;
            int row = f4 >> 3;
            int kk = (f4 & 7) * 4;
            float4 v = make_float4(0.f, 0.f, 0.f, 0.f);
            if (row0 + row < M) v = *(const float4*)&A[(size_t)(row0 + row) * 128 + k0 + kk];
            if (MODE == 1) {
                float4 p = *(const float4*)&pb[k0 + kk];
                v.x = elu(v.x + p.x); v.y = elu(v.y + p.y);
                v.z = elu(v.z + p.z); v.w = elu(v.w + p.w);
            }
            *(float4*)&As[row * 36 + kk] = v;
        }
        // stage W tile (32 rows x 128 cols), pad 132
        #pragma unroll
        for (int u = 0; u < 4; u++) {
            int f4 = u * 256 + tid;
            int kr = f4 >> 5;
            int c4 = (f4 & 31) * 4;
            float4 v = *(const float4*)&W[(size_t)(kr + k0) * 128 + c4];
            *(float4*)&Ws[kr * 132 + c4] = v;
        }
        __syncthreads();
        #pragma unroll
        for (int k = 0; k < 32; k++) {
            float a[8];
            #pragma unroll
            for (int ii = 0; ii < 8; ii++) a[ii] = As[(ty * 8 + ii) * 36 + k];
            float4 b0 = *(float4*)&Ws[k * 132 + tx * 8];
            float4 b1v = *(float4*)&Ws[k * 132 + tx * 8 + 4];
            float b[8] = {b0.x, b0.y, b0.z, b0.w, b1v.x, b1v.y, b1v.z, b1v.w};
            #pragma unroll
            for (int ii = 0; ii < 8; ii++)
                #pragma unroll
                for (int jj = 0; jj < 8; jj++) acc[ii][jj] += a[ii] * b[jj];
        }
        __syncthreads();
    }

    if (MODE == 0) {
        const float* bias = g_bc + r * HD;
        float4 bl0 = *(const float4*)&bias[tx * 8];
        float4 bl1 = *(const float4*)&bias[tx * 8 + 4];
        float bb[8] = {bl0.x, bl0.y, bl0.z, bl0.w, bl1.x, bl1.y, bl1.z, bl1.w};
        float* C = g_hs + (size_t)r * NN * HD;
        #pragma unroll
        for (int ii = 0; ii < 8; ii++) {
            int row = row0 + ty * 8 + ii;
            if (row < M) {
                float4 o0 = make_float4(acc[ii][0] + bb[0], acc[ii][1] + bb[1],
                                        acc[ii][2] + bb[2], acc[ii][3] + bb[3]);
                float4 o1 = make_float4(acc[ii][4] + bb[4], acc[ii][5] + bb[5],
                                        acc[ii][6] + bb[6], acc[ii][7] + bb[7]);
                *(float4*)&C[(size_t)row * 128 + tx * 8] = o0;
                *(float4*)&C[(size_t)row * 128 + tx * 8 + 4] = o1;
            }
        }
    } else {
        float4 b0 = *(const float4*)&b1[tx * 8];
        float4 b1v = *(const float4*)&b1[tx * 8 + 4];
        float bb[8] = {b0.x, b0.y, b0.z, b0.w, b1v.x, b1v.y, b1v.z, b1v.w};
        float4 w0 = *(const float4*)&W2[tx * 8];
        float4 w1 = *(const float4*)&W2[tx * 8 + 4];
        float ww[8] = {w0.x, w0.y, w0.z, w0.w, w1.x, w1.y, w1.z, w1.w};
        if (tid < 128) wrow[tid] = 0.f;
        __syncthreads();
        #pragma unroll
        for (int ii = 0; ii < 8; ii++) {
            int row = row0 + ty * 8 + ii;
            if (row < M) {
                float wp = 0.f;
                #pragma unroll
                for (int jj = 0; jj < 8; jj++)
                    wp += tanhf(acc[ii][jj] + bb[jj]) * ww[jj];
                atomicAdd(&wrow[ty * 8 + ii], wp);
            }
        }
        __syncthreads();
        if (tid < 128) {
            float v = wrow[tid];
            #pragma unroll
            for (int off = 16; off > 0; off >>= 1)
                v += __shfl_xor_sync(0xffffffffu, v, off);
            if ((tid & 31) == 0) atomicAdd(&g_wsum[r], v);
        }
    }
}

// ---------------- el / er ----------------
__global__ void el_er_kernel(const float* __restrict__ dst_feat,
                             const float* __restrict__ attn_l) {
    __shared__ float s_url[RR * HH * HID];
    __shared__ float s_al[RR * HH * DD];
    __shared__ float s_erc[RR * HH];
    int tid = threadIdx.x;
    for (int i = tid; i < RR * HH * HID; i += 256) s_url[i] = g_url[i];
    for (int i = tid; i < RR * HH * DD; i += 256) s_al[i] = attn_l[i];
    if (tid < RR * HH) s_erc[tid] = g_erc[tid];
    __syncthreads();

    int warp = tid >> 5, lane = tid & 31;
    int n = blockIdx.x * 8 + warp;
    if (n >= NN) return;

    float4 df = *(const float4*)&dst_feat[(size_t)n * HID + lane * 4];
    #pragma unroll
    for (int rh = 0; rh < RR * HH; rh++) {
        const float* u = &s_url[rh * HID + lane * 4];
        float p = df.x * u[0] + df.y * u[1] + df.z * u[2] + df.w * u[3];
        #pragma unroll
        for (int off = 16; off > 0; off >>= 1)
            p += __shfl_xor_sync(0xffffffffu, p, off);
        if (lane == 0) {
            int r = rh >> 2, h = rh & 3;
            g_er[((size_t)r * NN + n) * HH + h] = p + s_erc[rh];
        }
    }
    int h = lane >> 3;
    #pragma unroll
    for (int r = 0; r < RR; r++) {
        float4 hv = *(const float4*)&g_hs[((size_t)r * NN + n) * HD + lane * 4];
        const float* a = &s_al[(r * HH + h) * DD + (lane & 7) * 4];
        float p = hv.x * a[0] + hv.y * a[1] + hv.z * a[2] + hv.w * a[3];
        p += __shfl_down_sync(0xffffffffu, p, 4, 8);
        p += __shfl_down_sync(0xffffffffu, p, 2, 8);
        p += __shfl_down_sync(0xffffffffu, p, 1, 8);
        if ((lane & 7) == 0) g_el[((size_t)r * NN + n) * HH + h] = p;
    }
}

// ---------------- edge passes ----------------
__global__ void edge_pass1(const int* __restrict__ si, const int* __restrict__ di) {
    int idx = blockIdx.x * blockDim.x + threadIdx.x;
    if (idx >= RR * EE) return;
    int r = idx / EE;
    int s = si[idx], d = di[idx];
    float4 el = *(const float4*)&g_el[((size_t)r * NN + s) * HH];
    float4 er = *(const float4*)&g_er[((size_t)r * NN + d) * HH];
    float e0 = lrelu(el.x + er.x);
    float e1 = lrelu(el.y + er.y);
    float e2 = lrelu(el.z + er.z);
    float e3 = lrelu(el.w + er.w);
    *(float4*)&g_e[(size_t)idx * HH] = make_float4(e0, e1, e2, e3);
    float* mp = &g_m[((size_t)r * NN + d) * HH];
    atomicMaxF(mp + 0, e0); atomicMaxF(mp + 1, e1);
    atomicMaxF(mp + 2, e2); atomicMaxF(mp + 3, e3);
}

__global__ void edge_pass2(const int* __restrict__ di) {
    int idx = blockIdx.x * blockDim.x + threadIdx.x;
    if (idx >= RR * EE) return;
    int r = idx / EE;
    int d = di[idx];
    float4 ev = *(const float4*)&g_e[(size_t)idx * HH];
    float4 mv = *(const float4*)&g_m[((size_t)r * NN + d) * HH];
    float x0 = expf(ev.x - mv.x);
    float x1 = expf(ev.y - mv.y);
    float x2 = expf(ev.z - mv.z);
    float x3 = expf(ev.w - mv.w);
    *(float4*)&g_e[(size_t)idx * HH] = make_float4(x0, x1, x2, x3);
    float* sp = &g_ssum[((size_t)r * NN + d) * HH];
    atomicAdd(sp + 0, x0); atomicAdd(sp + 1, x1);
    atomicAdd(sp + 2, x2); atomicAdd(sp + 3, x3);
}

__global__ void edge_pass3(const int* __restrict__ si, const int* __restrict__ di) {
    int gw = (blockIdx.x * blockDim.x + threadIdx.x) >> 5;
    int lane = threadIdx.x & 31;
    if (gw >= RR * EE) return;
    int r = gw / EE;
    int s = si[gw], d = di[gw];
    float4 hv = *(const float4*)&g_hs[((size_t)r * NN + s) * HD + lane * 4];
    int h = lane >> 3;
    float ex = g_e[(size_t)gw * HH + h];
    float ss = g_ssum[((size_t)r * NN + d) * HH + h];
    float alpha = ex / (ss + 1e-9f);
    float* dst = &g_rst[((size_t)r * NN + d) * HD + lane * 4];
    atomicAdd(dst + 0, alpha * hv.x);
    atomicAdd(dst + 1, alpha * hv.y);
    atomicAdd(dst + 2, alpha * hv.z);
    atomicAdd(dst + 3, alpha * hv.w);
}

// ---------------- semantic softmax + output ----------------
__global__ void finalize_a(float* att_out) {
    if (threadIdx.x == 0) {
        float w[RR];
        float mx = -1e30f;
        for (int r = 0; r < RR; r++) { w[r] = g_wsum[r] / (float)NN; mx = fmaxf(mx, w[r]); }
        float s = 0.f;
        for (int r = 0; r < RR; r++) { w[r] = expf(w[r] - mx); s += w[r]; }
        for (int r = 0; r < RR; r++) {
            float a = w[r] / s;
            g_a[r] = a;
            if (att_out) att_out[r] = a;
        }
    }
}

__global__ void out_z_kernel(const float* __restrict__ bias_g, float* __restrict__ out) {
    int i = blockIdx.x * blockDim.x + threadIdx.x;
    if (i >= NN * HD) return;
    int j = i & 127;
    float s = 0.f;
    #pragma unroll
    for (int r = 0; r < RR; r++) {
        float v = g_rst[(size_t)r * NN * HD + i] + bias_g[r * HD + j];
        v = v > 0.f ? v : expm1f(v);
        s += g_a[r] * v;
    }
    out[i] = s;
}

// ---------------- launch ----------------
extern "C" void kernel_launch(void* const* d_in, const int* in_sizes, int n_in,
                              void* d_out, int out_size) {
    const float* dst_feat  = (const float*)d_in[0];
    const float* src_feats = (const float*)d_in[1];
    const int*   src_idx   = (const int*)d_in[2];
    const int*   dst_idx   = (const int*)d_in[3];
    const float* Wt_dst    = (const float*)d_in[4];
    const float* bt_dst    = (const float*)d_in[5];
    const float* Wt_src    = (const float*)d_in[6];
    const float* bt_src    = (const float*)d_in[7];
    const float* Wg        = (const float*)d_in[8];
    const float* attn_l    = (const float*)d_in[9];
    const float* attn_r    = (const float*)d_in[10];
    const float* bias_g    = (const float*)d_in[11];
    const float* W1        = (const float*)d_in[12];
    const float* b1        = (const float*)d_in[13];
    const float* W2        = (const float*)d_in[14];
    float* out = (float*)d_out;
    float* att_out = (out_size >= NN * HD + RR) ? out + (size_t)NN * HD : nullptr;

    init_kernel<<<2048, 256>>>();
    prep1<<<RR, 128>>>(Wg, attn_r, bt_src);
    prep2<<<dim3(HID + 1, RR), 128>>>(Wt_src, Wg, Wt_dst, bt_dst);

    // hs = src_feats @ Wc + bc
    gemm128_kernel<0><<<dim3((NN + 127) / 128, RR), 256>>>(
        src_feats, nullptr, nullptr, nullptr, nullptr, NN);

    el_er_kernel<<<(NN + 7) / 8, 256>>>(dst_feat, attn_l);

    edge_pass1<<<(RR * EE + 255) / 256, 256>>>(src_idx, dst_idx);
    edge_pass2<<<(RR * EE + 255) / 256, 256>>>(dst_idx);
    edge_pass3<<<(RR * EE * 32 + 255) / 256, 256>>>(src_idx, dst_idx);

    // semantic attention scores
    gemm128_kernel<1><<<dim3((NN + 127) / 128, RR), 256>>>(
        nullptr, W1, b1, bias_g, W2, NN);

    finalize_a<<<1, 32>>>(att_out);
    out_z_kernel<<<(NN * HD + 255) / 256, 256>>>(bias_g, out);
}

// round 2
// speedup vs baseline: 1.2192x; 1.2192x over previous
#include <cuda_runtime.h>
#include <cuda_bf16.h>
#include <math.h>

#define NN 100000
#define RR 3
#define EE 320000
#define HH 4
#define DD 32
#define HD 128   // H*D
#define HID 128

typedef unsigned long long u64;

// ---------------- device scratch (no allocs allowed) ----------------
__device__ __align__(16) float g_hs  [RR * NN * HD];   // per-relation projected src features
__device__ __align__(16) float g_rst [RR * NN * HD];   // aggregation accumulator / z_r
__device__ __align__(16) float g_el  [RR * NN * HH];
__device__ __align__(16) float g_er  [RR * NN * HH];
__device__ __align__(16) float g_m   [RR * NN * HH];
__device__ __align__(16) float g_ssum[RR * NN * HH];
__device__ __align__(16) float g_e   [RR * EE * HH];   // edge scores then exp values
__device__ __align__(16) float g_Wc  [RR * HID * HD];  // fused src weight
__device__ __align__(16) float g_bc  [RR * HD];        // fused src bias
__device__ __align__(16) float g_gvec[RR * HID * HH];  // Wg contracted with attn_r
__device__ __align__(16) float g_url [RR * HH * HID];  // er projection vectors
__device__ __align__(16) float g_erc [RR * HH];        // er consts
__device__ float g_wsum[RR];
__device__ float g_a[RR];

// ---------------- helpers ----------------
__device__ __forceinline__ float lrelu(float x) { return x > 0.f ? x : 0.2f * x; }
__device__ __forceinline__ float elu(float x)   { return x > 0.f ? x : expm1f(x); }

__device__ __forceinline__ void atomicMaxF(float* addr, float v) {
    if (v >= 0.f) atomicMax((int*)addr, __float_as_int(v));
    else          atomicMin((unsigned int*)addr, __float_as_uint(v));
}

// packed f32x2 FMA (Blackwell double-rate fp32; ptxas never emits from C++)
__device__ __forceinline__ void fma2(u64& d, u64 a, u64 b) {
    asm("fma.rn.f32x2 %0, %1, %2, %0;" : "+l"(d) : "l"(a), "l"(b));
}
__device__ __forceinline__ u64 dup2(float x) {
    u64 r; asm("mov.b64 %0, {%1, %1};" : "=l"(r) : "f"(x)); return r;
}
__device__ __forceinline__ float2 unpack2(u64 v) {
    float2 f; asm("mov.b64 {%0, %1}, %2;" : "=f"(f.x), "=f"(f.y) : "l"(v)); return f;
}

// ---------------- init ----------------
__global__ void init_kernel() {
    int g = blockIdx.x * blockDim.x + threadIdx.x;
    int stride = gridDim.x * blockDim.x;
    float4 z4 = make_float4(0.f, 0.f, 0.f, 0.f);
    float4* rst4 = (float4*)g_rst;
    for (int i = g; i < RR * NN * HD / 4; i += stride) rst4[i] = z4;
    float4* s4 = (float4*)g_ssum;
    float4* m4 = (float4*)g_m;
    float4 mi = make_float4(-INFINITY, -INFINITY, -INFINITY, -INFINITY);
    for (int i = g; i < RR * NN * HH / 4; i += stride) { m4[i] = mi; s4[i] = z4; }
    if (g < RR) g_wsum[g] = 0.f;
}

// ---------------- weight prep ----------------
__global__ void prep1(const float* __restrict__ Wg, const float* __restrict__ attn_r,
                      const float* __restrict__ bt_src) {
    int r = blockIdx.x;
    int t = threadIdx.x;
    const float* wgr = Wg + (size_t)r * HID * HD;
    #pragma unroll
    for (int h = 0; h < HH; h++) {
        float s = 0.f;
        #pragma unroll
        for (int d = 0; d < DD; d++)
            s += wgr[t * HD + h * DD + d] * attn_r[(r * HH + h) * DD + d];
        g_gvec[(r * HID + t) * HH + h] = s;
    }
    float s = 0.f;
    for (int tt = 0; tt < HID; tt++) s += bt_src[r * HID + tt] * wgr[tt * HD + t];
    g_bc[r * HD + t] = s;
}

__global__ void prep2(const float* __restrict__ Wt_src, const float* __restrict__ Wg,
                      const float* __restrict__ Wt_dst, const float* __restrict__ bt_dst) {
    int k = blockIdx.x;
    int r = blockIdx.y;
    int j = threadIdx.x;
    if (k < HID) {
        __shared__ float arow[HID];
        arow[j] = Wt_src[((size_t)r * HID + k) * HID + j];
        __syncthreads();
        float s = 0.f;
        const float* wgr = Wg + (size_t)r * HID * HD;
        for (int t = 0; t < HID; t++) s += arow[t] * wgr[t * HD + j];
        g_Wc[((size_t)r * HID + k) * HD + j] = s;
    } else {
        int t = j;
        #pragma unroll
        for (int h = 0; h < HH; h++) {
            float s = 0.f;
            for (int tp = 0; tp < HID; tp++)
                s += Wt_dst[t * HID + tp] * g_gvec[(r * HID + tp) * HH + h];
            g_url[(r * HH + h) * HID + t] = s;
        }
        if (t < HH) {
            int h = t;
            float s = 0.f;
            for (int tp = 0; tp < HID; tp++)
                s += bt_dst[tp] * g_gvec[(r * HID + tp) * HH + h];
            g_erc[r * HH + h] = s;
        }
    }
}

// ---------------- big GEMM with f32x2 FMAs ----------------
// MODE 0: C = A@Wc + bc  (+ fused el = (C*attn_l).sum per head)
// MODE 1: semantic: A-load applies elu(x + bias_g), epilogue tanh@W2 row-reduce
template <int MODE>
__global__ __launch_bounds__(256, 2)
void gemm128_kernel(const float* __restrict__ Abase,
                    const float* __restrict__ Wext,
                    const float* __restrict__ b1,
                    const float* __restrict__ prebias,
                    const float* __restrict__ W2,
                    const float* __restrict__ attn_l,
                    int M) {
    __shared__ __align__(16) float As[128 * 36];
    __shared__ __align__(16) float Ws[32 * 132];
    __shared__ float wrow[128];

    int r = blockIdx.y;
    const float* A;
    const float* W;
    const float* pb = nullptr;
    if (MODE == 0) {
        A = Abase + (size_t)r * NN * HID;
        W = g_Wc + (size_t)r * HID * HD;
    } else {
        A = g_rst + (size_t)r * NN * HD;
        W = Wext;
        pb = prebias + r * HD;
    }

    int tid = threadIdx.x;
    int tx = tid & 15, ty = tid >> 4;
    int row0 = blockIdx.x * 128;

    u64 acc2[8][4];
    #pragma unroll
    for (int i = 0; i < 8; i++)
        #pragma unroll
        for (int j = 0; j < 4; j++) acc2[i][j] = 0ull;

    for (int k0 = 0; k0 < 128; k0 += 32) {
        #pragma unroll
        for (int u = 0; u < 4; u++) {
            int f4 = u * 256 + tid;
            int row = f4 >> 3;
            int kk = (f4 & 7) * 4;
            float4 v = make_float4(0.f, 0.f, 0.f, 0.f);
            if (row0 + row < M) v = *(const float4*)&A[(size_t)(row0 + row) * 128 + k0 + kk];
            if (MODE == 1) {
                float4 p = *(const float4*)&pb[k0 + kk];
                v.x = elu(v.x + p.x); v.y = elu(v.y + p.y);
                v.z = elu(v.z + p.z); v.w = elu(v.w + p.w);
            }
            *(float4*)&As[row * 36 + kk] = v;
        }
        #pragma unroll
        for (int u = 0; u < 4; u++) {
            int f4 = u * 256 + tid;
            int kr = f4 >> 5;
            int c4 = (f4 & 31) * 4;
            float4 v = *(const float4*)&W[(size_t)(kr + k0) * 128 + c4];
            *(float4*)&Ws[kr * 132 + c4] = v;
        }
        __syncthreads();
        #pragma unroll
        for (int k = 0; k < 32; k++) {
            u64 av[8];
            #pragma unroll
            for (int ii = 0; ii < 8; ii++) av[ii] = dup2(As[(ty * 8 + ii) * 36 + k]);
            const u64* bp = (const u64*)&Ws[k * 132 + tx * 8];
            u64 bv[4];
            #pragma unroll
            for (int j = 0; j < 4; j++) bv[j] = bp[j];
            #pragma unroll
            for (int ii = 0; ii < 8; ii++)
                #pragma unroll
                for (int jj = 0; jj < 4; jj++) fma2(acc2[ii][jj], av[ii], bv[jj]);
        }
        __syncthreads();
    }

    if (MODE == 0) {
        const float* bias = g_bc + r * HD;
        float4 bl0 = *(const float4*)&bias[tx * 8];
        float4 bl1 = *(const float4*)&bias[tx * 8 + 4];
        float bb[8] = {bl0.x, bl0.y, bl0.z, bl0.w, bl1.x, bl1.y, bl1.z, bl1.w};
        // attn_l slice for this thread's 8 columns (all inside one head)
        int h = tx >> 2;
        float al[8];
        #pragma unroll
        for (int jj = 0; jj < 8; jj++)
            al[jj] = attn_l[(r * HH + h) * DD + (tx & 3) * 8 + jj];
        float* C = g_hs + (size_t)r * NN * HD;
        #pragma unroll
        for (int ii = 0; ii < 8; ii++) {
            int row = row0 + ty * 8 + ii;
            float o[8];
            #pragma unroll
            for (int j2 = 0; j2 < 4; j2++) {
                float2 p = unpack2(acc2[ii][j2]);
                o[2 * j2] = p.x + bb[2 * j2];
                o[2 * j2 + 1] = p.y + bb[2 * j2 + 1];
            }
            float elp = 0.f;
            #pragma unroll
            for (int jj = 0; jj < 8; jj++) elp += o[jj] * al[jj];
            // reduce across the 4 lanes sharing (row, h): lanes are consecutive
            elp += __shfl_down_sync(0xffffffffu, elp, 2, 4);
            elp += __shfl_down_sync(0xffffffffu, elp, 1, 4);
            if (row < M) {
                *(float4*)&C[(size_t)row * 128 + tx * 8] = make_float4(o[0], o[1], o[2], o[3]);
                *(float4*)&C[(size_t)row * 128 + tx * 8 + 4] = make_float4(o[4], o[5], o[6], o[7]);
                if ((tx & 3) == 0)
                    g_el[((size_t)r * NN + row) * HH + h] = elp;
            }
        }
    } else {
        float4 b0 = *(const float4*)&b1[tx * 8];
        float4 b1v = *(const float4*)&b1[tx * 8 + 4];
        float bb[8] = {b0.x, b0.y, b0.z, b0.w, b1v.x, b1v.y, b1v.z, b1v.w};
        float4 w0 = *(const float4*)&W2[tx * 8];
        float4 w1 = *(const float4*)&W2[tx * 8 + 4];
        float ww[8] = {w0.x, w0.y, w0.z, w0.w, w1.x, w1.y, w1.z, w1.w};
        if (tid < 128) wrow[tid] = 0.f;
        __syncthreads();
        #pragma unroll
        for (int ii = 0; ii < 8; ii++) {
            int row = row0 + ty * 8 + ii;
            if (row < M) {
                float wp = 0.f;
                #pragma unroll
                for (int j2 = 0; j2 < 4; j2++) {
                    float2 p = unpack2(acc2[ii][j2]);
                    wp += tanhf(p.x + bb[2 * j2]) * ww[2 * j2];
                    wp += tanhf(p.y + bb[2 * j2 + 1]) * ww[2 * j2 + 1];
                }
                atomicAdd(&wrow[ty * 8 + ii], wp);
            }
        }
        __syncthreads();
        if (tid < 128) {
            float v = wrow[tid];
            #pragma unroll
            for (int off = 16; off > 0; off >>= 1)
                v += __shfl_xor_sync(0xffffffffu, v, off);
            if ((tid & 31) == 0) atomicAdd(&g_wsum[r], v);
        }
    }
}

// ---------------- er only (el fused into gemm0) ----------------
__global__ void er_kernel(const float* __restrict__ dst_feat) {
    __shared__ float s_url[RR * HH * HID];
    __shared__ float s_erc[RR * HH];
    int tid = threadIdx.x;
    for (int i = tid; i < RR * HH * HID; i += 256) s_url[i] = g_url[i];
    if (tid < RR * HH) s_erc[tid] = g_erc[tid];
    __syncthreads();

    int warp = tid >> 5, lane = tid & 31;
    int n = blockIdx.x * 8 + warp;
    if (n >= NN) return;

    float4 df = *(const float4*)&dst_feat[(size_t)n * HID + lane * 4];
    #pragma unroll
    for (int rh = 0; rh < RR * HH; rh++) {
        const float* u = &s_url[rh * HID + lane * 4];
        float p = df.x * u[0] + df.y * u[1] + df.z * u[2] + df.w * u[3];
        #pragma unroll
        for (int off = 16; off > 0; off >>= 1)
            p += __shfl_xor_sync(0xffffffffu, p, off);
        if (lane == 0) {
            int r = rh >> 2, h = rh & 3;
            g_er[((size_t)r * NN + n) * HH + h] = p + s_erc[rh];
        }
    }
}

// ---------------- edge passes ----------------
__global__ void edge_pass1(const int* __restrict__ si, const int* __restrict__ di) {
    int idx = blockIdx.x * blockDim.x + threadIdx.x;
    if (idx >= RR * EE) return;
    int r = idx / EE;
    int s = si[idx], d = di[idx];
    float4 el = *(const float4*)&g_el[((size_t)r * NN + s) * HH];
    float4 er = *(const float4*)&g_er[((size_t)r * NN + d) * HH];
    float e0 = lrelu(el.x + er.x);
    float e1 = lrelu(el.y + er.y);
    float e2 = lrelu(el.z + er.z);
    float e3 = lrelu(el.w + er.w);
    *(float4*)&g_e[(size_t)idx * HH] = make_float4(e0, e1, e2, e3);
    float* mp = &g_m[((size_t)r * NN + d) * HH];
    atomicMaxF(mp + 0, e0); atomicMaxF(mp + 1, e1);
    atomicMaxF(mp + 2, e2); atomicMaxF(mp + 3, e3);
}

__global__ void edge_pass2(const int* __restrict__ di) {
    int idx = blockIdx.x * blockDim.x + threadIdx.x;
    if (idx >= RR * EE) return;
    int r = idx / EE;
    int d = di[idx];
    float4 ev = *(const float4*)&g_e[(size_t)idx * HH];
    float4 mv = *(const float4*)&g_m[((size_t)r * NN + d) * HH];
    float x0 = expf(ev.x - mv.x);
    float x1 = expf(ev.y - mv.y);
    float x2 = expf(ev.z - mv.z);
    float x3 = expf(ev.w - mv.w);
    *(float4*)&g_e[(size_t)idx * HH] = make_float4(x0, x1, x2, x3);
    float* sp = &g_ssum[((size_t)r * NN + d) * HH];
    atomicAdd(sp + 0, x0); atomicAdd(sp + 1, x1);
    atomicAdd(sp + 2, x2); atomicAdd(sp + 3, x3);
}

__global__ void edge_pass3(const int* __restrict__ si, const int* __restrict__ di) {
    int gw = (blockIdx.x * blockDim.x + threadIdx.x) >> 5;
    int lane = threadIdx.x & 31;
    if (gw >= RR * EE) return;
    int r = gw / EE;
    int s = si[gw], d = di[gw];
    float4 hv = *(const float4*)&g_hs[((size_t)r * NN + s) * HD + lane * 4];
    int h = lane >> 3;
    float ex = g_e[(size_t)gw * HH + h];
    float ss = g_ssum[((size_t)r * NN + d) * HH + h];
    float alpha = ex / (ss + 1e-9f);
    float* dst = &g_rst[((size_t)r * NN + d) * HD + lane * 4];
    asm volatile("red.global.add.v4.f32 [%0], {%1, %2, %3, %4};"
                 :: "l"(dst), "f"(alpha * hv.x), "f"(alpha * hv.y),
                    "f"(alpha * hv.z), "f"(alpha * hv.w)
                 : "memory");
}

// ---------------- semantic softmax + output ----------------
__global__ void finalize_a(float* att_out) {
    if (threadIdx.x == 0) {
        float w[RR];
        float mx = -1e30f;
        for (int r = 0; r < RR; r++) { w[r] = g_wsum[r] / (float)NN; mx = fmaxf(mx, w[r]); }
        float s = 0.f;
        for (int r = 0; r < RR; r++) { w[r] = expf(w[r] - mx); s += w[r]; }
        for (int r = 0; r < RR; r++) {
            float a = w[r] / s;
            g_a[r] = a;
            if (att_out) att_out[r] = a;
        }
    }
}

__global__ void out_z_kernel(const float* __restrict__ bias_g, float* __restrict__ out) {
    int i = blockIdx.x * blockDim.x + threadIdx.x;
    if (i >= NN * HD) return;
    int j = i & 127;
    float s = 0.f;
    #pragma unroll
    for (int r = 0; r < RR; r++) {
        float v = g_rst[(size_t)r * NN * HD + i] + bias_g[r * HD + j];
        v = v > 0.f ? v : expm1f(v);
        s += g_a[r] * v;
    }
    out[i] = s;
}

// ---------------- launch ----------------
extern "C" void kernel_launch(void* const* d_in, const int* in_sizes, int n_in,
                              void* d_out, int out_size) {
    const float* dst_feat  = (const float*)d_in[0];
    const float* src_feats = (const float*)d_in[1];
    const int*   src_idx   = (const int*)d_in[2];
    const int*   dst_idx   = (const int*)d_in[3];
    const float* Wt_dst    = (const float*)d_in[4];
    const float* bt_dst    = (const float*)d_in[5];
    const float* Wt_src    = (const float*)d_in[6];
    const float* bt_src    = (const float*)d_in[7];
    const float* Wg        = (const float*)d_in[8];
    const float* attn_l    = (const float*)d_in[9];
    const float* attn_r    = (const float*)d_in[10];
    const float* bias_g    = (const float*)d_in[11];
    const float* W1        = (const float*)d_in[12];
    const float* b1        = (const float*)d_in[13];
    const float* W2        = (const float*)d_in[14];
    float* out = (float*)d_out;
    float* att_out = (out_size >= NN * HD + RR) ? out + (size_t)NN * HD : nullptr;

    init_kernel<<<2048, 256>>>();
    prep1<<<RR, 128>>>(Wg, attn_r, bt_src);
    prep2<<<dim3(HID + 1, RR), 128>>>(Wt_src, Wg, Wt_dst, bt_dst);

    // hs = src_feats @ Wc + bc (+ fused el)
    gemm128_kernel<0><<<dim3((NN + 127) / 128, RR), 256>>>(
        src_feats, nullptr, nullptr, nullptr, nullptr, attn_l, NN);

    er_kernel<<<(NN + 7) / 8, 256>>>(dst_feat);

    edge_pass1<<<(RR * EE + 255) / 256, 256>>>(src_idx, dst_idx);
    edge_pass2<<<(RR * EE + 255) / 256, 256>>>(dst_idx);
    edge_pass3<<<(RR * EE * 32 + 255) / 256, 256>>>(src_idx, dst_idx);

    // semantic attention scores
    gemm128_kernel<1><<<dim3((NN + 127) / 128, RR), 256>>>(
        nullptr, W1, b1, bias_g, W2, nullptr, NN);

    finalize_a<<<1, 32>>>(att_out);
    out_z_kernel<<<(NN * HD + 255) / 256, 256>>>(bias_g, out);
}

// round 4
// speedup vs baseline: 1.4323x; 1.1747x over previous
#include <cuda_runtime.h>
#include <cuda_bf16.h>
#include <math.h>
#include <stdint.h>

#define NN 100000
#define RR 3
#define EE 320000
#define HH 4
#define DD 32
#define HD 128   // H*D
#define HID 128

// ---------------- device scratch (no allocs allowed) ----------------
__device__ __align__(16) float g_hs  [RR * NN * HD];
__device__ __align__(16) float g_rst [RR * NN * HD];
__device__ __align__(16) float g_el  [RR * NN * HH];
__device__ __align__(16) float g_er  [RR * NN * HH];
__device__ __align__(16) float g_m   [RR * NN * HH];
__device__ __align__(16) float g_ssum[RR * NN * HH];
__device__ __align__(16) float g_e   [RR * EE * HH];
__device__ __align__(16) float g_Wc  [RR * HID * HD];
__device__ __align__(16) float g_bc  [RR * HD];
__device__ __align__(16) float g_gvec[RR * HID * HH];
__device__ __align__(16) float g_url [RR * HH * HID];
__device__ __align__(16) float g_erc [RR * HH];
__device__ float g_wsum[RR];
__device__ float g_a[RR];

// Prebuilt bf16 B tiles (col-major k x n == stored [n][k]), padded stride 136.
// [mat 0..2 = Wc[r], 3 = W1] x [hi, lo] x 128 n-rows x 136 k-elems
#define BSTR 136
__device__ __align__(16) __nv_bfloat16 g_Bt[4][2][128 * BSTR];

// ---------------- helpers ----------------
__device__ __forceinline__ float lrelu(float x) { return x > 0.f ? x : 0.2f * x; }
__device__ __forceinline__ float elu(float x)   { return x > 0.f ? x : expm1f(x); }

__device__ __forceinline__ void atomicMaxF(float* addr, float v) {
    if (v >= 0.f) atomicMax((int*)addr, __float_as_int(v));
    else          atomicMin((unsigned int*)addr, __float_as_uint(v));
}

__device__ __forceinline__ uint32_t smem_to_u32(const void* p) {
    uint32_t a;
    asm("{ .reg .u64 t; cvta.to.shared.u64 t, %1; cvt.u32.u64 %0, t; }" : "=r"(a) : "l"(p));
    return a;
}
__device__ __forceinline__ void ldsm4(uint32_t* r, uint32_t addr) {
    asm volatile("ldmatrix.sync.aligned.m8n8.x4.shared.b16 {%0,%1,%2,%3}, [%4];"
                 : "=r"(r[0]), "=r"(r[1]), "=r"(r[2]), "=r"(r[3]) : "r"(addr));
}
__device__ __forceinline__ void mma_bf16(float* d, const uint32_t* a,
                                         uint32_t b0, uint32_t b1) {
    asm volatile("mma.sync.aligned.m16n8k16.row.col.f32.bf16.bf16.f32 "
                 "{%0,%1,%2,%3}, {%4,%5,%6,%7}, {%8,%9}, {%0,%1,%2,%3};"
                 : "+f"(d[0]), "+f"(d[1]), "+f"(d[2]), "+f"(d[3])
                 : "r"(a[0]), "r"(a[1]), "r"(a[2]), "r"(a[3]), "r"(b0), "r"(b1));
}
__device__ __forceinline__ uint32_t pack_bf16(float a, float b) {
    __nv_bfloat162 t = __floats2bfloat162_rn(a, b);
    return *(uint32_t*)&t;
}

// ---------------- init ----------------
__global__ void init_kernel() {
    int g = blockIdx.x * blockDim.x + threadIdx.x;
    int stride = gridDim.x * blockDim.x;
    float4 z4 = make_float4(0.f, 0.f, 0.f, 0.f);
    float4* rst4 = (float4*)g_rst;
    for (int i = g; i < RR * NN * HD / 4; i += stride) rst4[i] = z4;
    float4* s4 = (float4*)g_ssum;
    float4* m4 = (float4*)g_m;
    float4 mi = make_float4(-INFINITY, -INFINITY, -INFINITY, -INFINITY);
    for (int i = g; i < RR * NN * HH / 4; i += stride) { m4[i] = mi; s4[i] = z4; }
    if (g < RR) g_wsum[g] = 0.f;
}

// ---------------- weight prep ----------------
__global__ void prep1(const float* __restrict__ Wg, const float* __restrict__ attn_r,
                      const float* __restrict__ bt_src) {
    int r = blockIdx.x;
    int t = threadIdx.x;
    const float* wgr = Wg + (size_t)r * HID * HD;
    #pragma unroll
    for (int h = 0; h < HH; h++) {
        float s = 0.f;
        #pragma unroll
        for (int d = 0; d < DD; d++)
            s += wgr[t * HD + h * DD + d] * attn_r[(r * HH + h) * DD + d];
        g_gvec[(r * HID + t) * HH + h] = s;
    }
    float s = 0.f;
    for (int tt = 0; tt < HID; tt++) s += bt_src[r * HID + tt] * wgr[tt * HD + t];
    g_bc[r * HD + t] = s;
}

__global__ void prep2(const float* __restrict__ Wt_src, const float* __restrict__ Wg,
                      const float* __restrict__ Wt_dst, const float* __restrict__ bt_dst) {
    int k = blockIdx.x;
    int r = blockIdx.y;
    int j = threadIdx.x;
    if (k < HID) {
        __shared__ float arow[HID];
        arow[j] = Wt_src[((size_t)r * HID + k) * HID + j];
        __syncthreads();
        float s = 0.f;
        const float* wgr = Wg + (size_t)r * HID * HD;
        for (int t = 0; t < HID; t++) s += arow[t] * wgr[t * HD + j];
        g_Wc[((size_t)r * HID + k) * HD + j] = s;
    } else {
        int t = j;
        #pragma unroll
        for (int h = 0; h < HH; h++) {
            float s = 0.f;
            for (int tp = 0; tp < HID; tp++)
                s += Wt_dst[t * HID + tp] * g_gvec[(r * HID + tp) * HH + h];
            g_url[(r * HH + h) * HID + t] = s;
        }
        if (t < HH) {
            int h = t;
            float s = 0.f;
            for (int tp = 0; tp < HID; tp++)
                s += bt_dst[tp] * g_gvec[(r * HID + tp) * HH + h];
            g_erc[r * HH + h] = s;
        }
    }
}

// Build bf16 hi/lo B tiles: Bt[mat][.][n][k] = W[k][n]; mats 0..2 = g_Wc[r], 3 = W1.
__global__ void prep_b(const float* __restrict__ W1) {
    int idx = blockIdx.x * blockDim.x + threadIdx.x;   // 4 * 128 * 128
    if (idx >= 4 * 128 * 128) return;
    int mat = idx >> 14;
    int e = idx & 16383;
    int n = e >> 7;
    int k = e & 127;
    float w = (mat < 3) ? g_Wc[((size_t)mat * HID + k) * HD + n] : W1[k * 128 + n];
    __nv_bfloat16 hi = __float2bfloat16(w);
    __nv_bfloat16 lo = __float2bfloat16(w - __bfloat162float(hi));
    g_Bt[mat][0][n * BSTR + k] = hi;
    g_Bt[mat][1][n * BSTR + k] = lo;
}

// ---------------- mma.sync GEMM ----------------
// Dynamic smem layout (bytes):
//   As_hi [128][136] bf16 @ 0        (34816 B)
//   As_lo                @ 34816
//   Bs_hi [128][136] bf16 @ 69632
//   Bs_lo                @ 104448
#define A_HI_OFF 0
#define A_LO_OFF 34816
#define B_OFF    69632
#define GEMM_SMEM (69632 * 2)

// MODE 0: C = A@Wc + bc (+ fused per-head el).  A = src_feats[r], B = g_Bt[r]
// MODE 1: semantic: A = elu(g_rst[r] + bias_g[r]), B = g_Bt[3]; tanh@W2 row-reduce.
template <int MODE>
__global__ __launch_bounds__(512, 1)
void gemm_mma(const float* __restrict__ Abase,
              const float* __restrict__ b1,
              const float* __restrict__ prebias,
              const float* __restrict__ W2,
              const float* __restrict__ attn_l,
              int M) {
    extern __shared__ __align__(16) char smem[];
    __shared__ float wrow[128];
    uint32_t sb = smem_to_u32(smem);
    int tid = threadIdx.x;
    int w = tid >> 5, lane = tid & 31;
    int r = blockIdx.y;
    int row0 = blockIdx.x * 128;

    const float* A = (MODE == 0) ? (Abase + (size_t)r * NN * HID)
                                 : (g_rst + (size_t)r * NN * HD);
    const float* pb = (MODE == 1) ? (prebias + r * HD) : nullptr;
    int mat = (MODE == 0) ? r : 3;

    // ---- stage B (copy prebuilt hi+lo bf16, 69632 B) ----
    {
        const uint4* src = (const uint4*)&g_Bt[mat][0][0];
        uint4* dst = (uint4*)(smem + B_OFF);
        for (int i = tid; i < 69632 / 16; i += 512) dst[i] = src[i];
    }
    // ---- stage A: fp32 -> bf16 hi/lo split ----
    for (int u = 0; u < 8; u++) {
        int g = u * 512 + tid;          // 4096 float4 groups
        int row = g >> 5;
        int k0 = (g & 31) * 4;
        float f[4];
        if (row0 + row < M) {
            float4 v = *(const float4*)&A[(size_t)(row0 + row) * 128 + k0];
            f[0] = v.x; f[1] = v.y; f[2] = v.z; f[3] = v.w;
            if (MODE == 1) {
                float4 p = *(const float4*)&pb[k0];
                f[0] = elu(f[0] + p.x); f[1] = elu(f[1] + p.y);
                f[2] = elu(f[2] + p.z); f[3] = elu(f[3] + p.w);
            }
        } else {
            f[0] = f[1] = f[2] = f[3] = 0.f;
        }
        float fh[4], fl[4];
        #pragma unroll
        for (int j = 0; j < 4; j++) {
            __nv_bfloat16 h = __float2bfloat16(f[j]);
            fh[j] = __bfloat162float(h);
            fl[j] = f[j] - fh[j];
        }
        uint32_t off = (uint32_t)(row * BSTR + k0) * 2;
        *(uint2*)(smem + A_HI_OFF + off) = make_uint2(pack_bf16(fh[0], fh[1]), pack_bf16(fh[2], fh[3]));
        *(uint2*)(smem + A_LO_OFF + off) = make_uint2(pack_bf16(fl[0], fl[1]), pack_bf16(fl[2], fl[3]));
    }
    if (MODE == 1 && tid < 128) wrow[tid] = 0.f;
    __syncthreads();

    // ---- mma mainloop: warp = 16 rows x 64 cols ----
    int m0 = (w & 7) * 16;
    int n0 = (w >> 3) * 64;

    uint32_t a_hi_addr = sb + A_HI_OFF + ((m0 + (lane & 15)) * BSTR + (lane >> 4) * 8) * 2;
    uint32_t a_lo_addr = a_hi_addr + (A_LO_OFF - A_HI_OFF);
    int b_n = n0 + (lane & 7) + ((lane >> 4) & 1) * 8;
    int b_k = ((lane >> 3) & 1) * 8;
    uint32_t b_hi_base = sb + B_OFF + (b_n * BSTR + b_k) * 2;
    uint32_t b_lo_base = b_hi_base + 34816;

    float acc[8][4];
    #pragma unroll
    for (int i = 0; i < 8; i++)
        #pragma unroll
        for (int j = 0; j < 4; j++) acc[i][j] = 0.f;

    #pragma unroll
    for (int ks = 0; ks < 8; ks++) {
        uint32_t kb = ks * 32;   // k0 * 2 bytes
        uint32_t ah[4], al_[4];
        ldsm4(ah, a_hi_addr + kb);
        ldsm4(al_, a_lo_addr + kb);
        #pragma unroll
        for (int g = 0; g < 4; g++) {
            uint32_t bh[4], bl[4];
            ldsm4(bh, b_hi_base + g * (16 * BSTR * 2) + kb);
            ldsm4(bl, b_lo_base + g * (16 * BSTR * 2) + kb);
            mma_bf16(acc[2 * g],     ah,  bh[0], bh[1]);
            mma_bf16(acc[2 * g + 1], ah,  bh[2], bh[3]);
            mma_bf16(acc[2 * g],     ah,  bl[0], bl[1]);
            mma_bf16(acc[2 * g + 1], ah,  bl[2], bl[3]);
            mma_bf16(acc[2 * g],     al_, bh[0], bh[1]);
            mma_bf16(acc[2 * g + 1], al_, bh[2], bh[3]);
        }
    }

    // ---- epilogue ----
    int rowA = row0 + m0 + (lane >> 2);
    int rowB = rowA + 8;

    if (MODE == 0) {
        float* C = g_hs + (size_t)r * NN * HD;
        float elA[2] = {0.f, 0.f}, elB[2] = {0.f, 0.f};
        #pragma unroll
        for (int f = 0; f < 8; f++) {
            int col = n0 + f * 8 + (lane & 3) * 2;
            int hl = f >> 2;                 // head-local (2 heads per warp)
            int head = (n0 >> 5) + hl;
            float bc0 = g_bc[r * HD + col], bc1 = g_bc[r * HD + col + 1];
            float al0 = attn_l[(r * HH + head) * DD + (col - head * 32)];
            float al1 = attn_l[(r * HH + head) * DD + (col + 1 - head * 32)];
            float o00 = acc[f][0] + bc0, o01 = acc[f][1] + bc1;
            float o10 = acc[f][2] + bc0, o11 = acc[f][3] + bc1;
            elA[hl] += o00 * al0 + o01 * al1;
            elB[hl] += o10 * al0 + o11 * al1;
            if (rowA < M) *(float2*)&C[(size_t)rowA * 128 + col] = make_float2(o00, o01);
            if (rowB < M) *(float2*)&C[(size_t)rowB * 128 + col] = make_float2(o10, o11);
        }
        #pragma unroll
        for (int hl = 0; hl < 2; hl++) {
            float va = elA[hl], vb = elB[hl];
            va += __shfl_xor_sync(0xffffffffu, va, 1);
            va += __shfl_xor_sync(0xffffffffu, va, 2);
            vb += __shfl_xor_sync(0xffffffffu, vb, 1);
            vb += __shfl_xor_sync(0xffffffffu, vb, 2);
            if ((lane & 3) == 0) {
                int head = (n0 >> 5) + hl;
                if (rowA < M) g_el[((size_t)r * NN + rowA) * HH + head] = va;
                if (rowB < M) g_el[((size_t)r * NN + rowB) * HH + head] = vb;
            }
        }
    } else {
        float wpA = 0.f, wpB = 0.f;
        #pragma unroll
        for (int f = 0; f < 8; f++) {
            int col = n0 + f * 8 + (lane & 3) * 2;
            float b0 = b1[col], bb1 = b1[col + 1];
            float w0 = W2[col], w1 = W2[col + 1];
            wpA += tanhf(acc[f][0] + b0) * w0 + tanhf(acc[f][1] + bb1) * w1;
            wpB += tanhf(acc[f][2] + b0) * w0 + tanhf(acc[f][3] + bb1) * w1;
        }
        wpA += __shfl_xor_sync(0xffffffffu, wpA, 1);
        wpA += __shfl_xor_sync(0xffffffffu, wpA, 2);
        wpB += __shfl_xor_sync(0xffffffffu, wpB, 1);
        wpB += __shfl_xor_sync(0xffffffffu, wpB, 2);
        if ((lane & 3) == 0) {
            if (rowA < M) atomicAdd(&wrow[m0 + (lane >> 2)], wpA);
            if (rowB < M) atomicAdd(&wrow[m0 + (lane >> 2) + 8], wpB);
        }
        __syncthreads();
        if (tid < 128) {
            float v = wrow[tid];
            #pragma unroll
            for (int off = 16; off > 0; off >>= 1)
                v += __shfl_xor_sync(0xffffffffu, v, off);
            if ((tid & 31) == 0) atomicAdd(&g_wsum[r], v);
        }
    }
}

// ---------------- er (el fused into gemm0) ----------------
__global__ void er_kernel(const float* __restrict__ dst_feat) {
    __shared__ float s_url[RR * HH * HID];
    __shared__ float s_erc[RR * HH];
    int tid = threadIdx.x;
    for (int i = tid; i < RR * HH * HID; i += 256) s_url[i] = g_url[i];
    if (tid < RR * HH) s_erc[tid] = g_erc[tid];
    __syncthreads();

    int warp = tid >> 5, lane = tid & 31;
    int n = blockIdx.x * 8 + warp;
    if (n >= NN) return;

    float4 df = *(const float4*)&dst_feat[(size_t)n * HID + lane * 4];
    #pragma unroll
    for (int rh = 0; rh < RR * HH; rh++) {
        const float* u = &s_url[rh * HID + lane * 4];
        float p = df.x * u[0] + df.y * u[1] + df.z * u[2] + df.w * u[3];
        #pragma unroll
        for (int off = 16; off > 0; off >>= 1)
            p += __shfl_xor_sync(0xffffffffu, p, off);
        if (lane == 0) {
            int r = rh >> 2, h = rh & 3;
            g_er[((size_t)r * NN + n) * HH + h] = p + s_erc[rh];
        }
    }
}

// ---------------- edge passes ----------------
__global__ void edge_pass1(const int* __restrict__ si, const int* __restrict__ di) {
    int idx = blockIdx.x * blockDim.x + threadIdx.x;
    if (idx >= RR * EE) return;
    int r = idx / EE;
    int s = si[idx], d = di[idx];
    float4 el = *(const float4*)&g_el[((size_t)r * NN + s) * HH];
    float4 er = *(const float4*)&g_er[((size_t)r * NN + d) * HH];
    float e0 = lrelu(el.x + er.x);
    float e1 = lrelu(el.y + er.y);
    float e2 = lrelu(el.z + er.z);
    float e3 = lrelu(el.w + er.w);
    *(float4*)&g_e[(size_t)idx * HH] = make_float4(e0, e1, e2, e3);
    float* mp = &g_m[((size_t)r * NN + d) * HH];
    atomicMaxF(mp + 0, e0); atomicMaxF(mp + 1, e1);
    atomicMaxF(mp + 2, e2); atomicMaxF(mp + 3, e3);
}

__global__ void edge_pass2(const int* __restrict__ di) {
    int idx = blockIdx.x * blockDim.x + threadIdx.x;
    if (idx >= RR * EE) return;
    int r = idx / EE;
    int d = di[idx];
    float4 ev = *(const float4*)&g_e[(size_t)idx * HH];
    float4 mv = *(const float4*)&g_m[((size_t)r * NN + d) * HH];
    float x0 = expf(ev.x - mv.x);
    float x1 = expf(ev.y - mv.y);
    float x2 = expf(ev.z - mv.z);
    float x3 = expf(ev.w - mv.w);
    *(float4*)&g_e[(size_t)idx * HH] = make_float4(x0, x1, x2, x3);
    float* sp = &g_ssum[((size_t)r * NN + d) * HH];
    atomicAdd(sp + 0, x0); atomicAdd(sp + 1, x1);
    atomicAdd(sp + 2, x2); atomicAdd(sp + 3, x3);
}

__global__ void edge_pass3(const int* __restrict__ si, const int* __restrict__ di) {
    int gw = (blockIdx.x * blockDim.x + threadIdx.x) >> 5;
    int lane = threadIdx.x & 31;
    if (gw >= RR * EE) return;
    int r = gw / EE;
    int s = si[gw], d = di[gw];
    float4 hv = *(const float4*)&g_hs[((size_t)r * NN + s) * HD + lane * 4];
    int h = lane >> 3;
    float ex = g_e[(size_t)gw * HH + h];
    float ss = g_ssum[((size_t)r * NN + d) * HH + h];
    float alpha = ex / (ss + 1e-9f);
    float* dst = &g_rst[((size_t)r * NN + d) * HD + lane * 4];
    asm volatile("red.global.add.v4.f32 [%0], {%1, %2, %3, %4};"
                 :: "l"(dst), "f"(alpha * hv.x), "f"(alpha * hv.y),
                    "f"(alpha * hv.z), "f"(alpha * hv.w)
                 : "memory");
}

// ---------------- semantic softmax + output ----------------
__global__ void finalize_a(float* att_out) {
    if (threadIdx.x == 0) {
        float w[RR];
        float mx = -1e30f;
        for (int r = 0; r < RR; r++) { w[r] = g_wsum[r] / (float)NN; mx = fmaxf(mx, w[r]); }
        float s = 0.f;
        for (int r = 0; r < RR; r++) { w[r] = expf(w[r] - mx); s += w[r]; }
        for (int r = 0; r < RR; r++) {
            float a = w[r] / s;
            g_a[r] = a;
            if (att_out) att_out[r] = a;
        }
    }
}

__global__ void out_z_kernel(const float* __restrict__ bias_g, float* __restrict__ out) {
    int i = blockIdx.x * blockDim.x + threadIdx.x;
    if (i >= NN * HD) return;
    int j = i & 127;
    float s = 0.f;
    #pragma unroll
    for (int r = 0; r < RR; r++) {
        float v = g_rst[(size_t)r * NN * HD + i] + bias_g[r * HD + j];
        v = v > 0.f ? v : expm1f(v);
        s += g_a[r] * v;
    }
    out[i] = s;
}

// ---------------- launch ----------------
extern "C" void kernel_launch(void* const* d_in, const int* in_sizes, int n_in,
                              void* d_out, int out_size) {
    const float* dst_feat  = (const float*)d_in[0];
    const float* src_feats = (const float*)d_in[1];
    const int*   src_idx   = (const int*)d_in[2];
    const int*   dst_idx   = (const int*)d_in[3];
    const float* Wt_dst    = (const float*)d_in[4];
    const float* bt_dst    = (const float*)d_in[5];
    const float* Wt_src    = (const float*)d_in[6];
    const float* bt_src    = (const float*)d_in[7];
    const float* Wg        = (const float*)d_in[8];
    const float* attn_l    = (const float*)d_in[9];
    const float* attn_r    = (const float*)d_in[10];
    const float* bias_g    = (const float*)d_in[11];
    const float* W1        = (const float*)d_in[12];
    const float* b1        = (const float*)d_in[13];
    const float* W2        = (const float*)d_in[14];
    float* out = (float*)d_out;
    float* att_out = (out_size >= NN * HD + RR) ? out + (size_t)NN * HD : nullptr;

    cudaFuncSetAttribute(gemm_mma<0>, cudaFuncAttributeMaxDynamicSharedMemorySize, GEMM_SMEM);
    cudaFuncSetAttribute(gemm_mma<1>, cudaFuncAttributeMaxDynamicSharedMemorySize, GEMM_SMEM);

    init_kernel<<<2048, 256>>>();
    prep1<<<RR, 128>>>(Wg, attn_r, bt_src);
    prep2<<<dim3(HID + 1, RR), 128>>>(Wt_src, Wg, Wt_dst, bt_dst);
    prep_b<<<(4 * 128 * 128 + 255) / 256, 256>>>(W1);

    int tiles = (NN + 127) / 128;

    gemm_mma<0><<<dim3(tiles, RR), 512, GEMM_SMEM>>>(
        src_feats, nullptr, nullptr, nullptr, attn_l, NN);

    er_kernel<<<(NN + 7) / 8, 256>>>(dst_feat);

    edge_pass1<<<(RR * EE + 255) / 256, 256>>>(src_idx, dst_idx);
    edge_pass2<<<(RR * EE + 255) / 256, 256>>>(dst_idx);
    edge_pass3<<<(RR * EE * 32 + 255) / 256, 256>>>(src_idx, dst_idx);

    gemm_mma<1><<<dim3(tiles, RR), 512, GEMM_SMEM>>>(
        nullptr, b1, bias_g, W2, nullptr, NN);

    finalize_a<<<1, 32>>>(att_out);
    out_z_kernel<<<(NN * HD + 255) / 256, 256>>>(bias_g, out);
}

// round 6
// speedup vs baseline: 1.5296x; 1.0680x over previous
#include <cuda_runtime.h>
#include <cuda_bf16.h>
#include <math.h>
#include <stdint.h>

#define NN 100000
#define RR 3
#define EE 320000
#define HH 4
#define DD 32
#define HD 128   // H*D
#define HID 128
#define NODES (RR * NN)
#define NEDGE (RR * EE)
#define SCAN_BLK 2048
#define NSCAN ((NODES + SCAN_BLK - 1) / SCAN_BLK)   // 147

// ---------------- device scratch (no allocs allowed) ----------------
__device__ __align__(16) float g_hs  [RR * NN * HD];
__device__ __align__(16) float g_rst [RR * NN * HD];
__device__ __align__(16) float g_el  [RR * NN * HH];
__device__ __align__(16) float g_er  [RR * NN * HH];
__device__ __align__(16) float g_Wc  [RR * HID * HD];
__device__ __align__(16) float g_bc  [RR * HD];
__device__ __align__(16) float g_gvec[RR * HID * HH];
__device__ __align__(16) float g_url [RR * HH * HID];
__device__ __align__(16) float g_erc [RR * HH];
__device__ float g_wsum[RR];
__device__ float g_a[RR];

// CSR scratch
__device__ int g_deg [NODES];
__device__ int g_ptr [NODES];
__device__ int g_bsum[NSCAN + 1];
__device__ int g_esrc[NEDGE];

// Prebuilt bf16 B tiles (stored [n][k]), padded stride 136.
#define BSTR 136
__device__ __align__(16) __nv_bfloat16 g_Bt[4][2][128 * BSTR];

// ---------------- helpers ----------------
__device__ __forceinline__ float lrelu(float x) { return x > 0.f ? x : 0.2f * x; }
__device__ __forceinline__ float elu(float x)   { return x > 0.f ? x : expm1f(x); }

__device__ __forceinline__ uint32_t smem_to_u32(const void* p) {
    uint32_t a;
    asm("{ .reg .u64 t; cvta.to.shared.u64 t, %1; cvt.u32.u64 %0, t; }" : "=r"(a) : "l"(p));
    return a;
}
__device__ __forceinline__ void ldsm4(uint32_t* r, uint32_t addr) {
    asm volatile("ldmatrix.sync.aligned.m8n8.x4.shared.b16 {%0,%1,%2,%3}, [%4];"
                 : "=r"(r[0]), "=r"(r[1]), "=r"(r[2]), "=r"(r[3]) : "r"(addr));
}
__device__ __forceinline__ void mma_bf16(float* d, const uint32_t* a,
                                         uint32_t b0, uint32_t b1) {
    asm volatile("mma.sync.aligned.m16n8k16.row.col.f32.bf16.bf16.f32 "
                 "{%0,%1,%2,%3}, {%4,%5,%6,%7}, {%8,%9}, {%0,%1,%2,%3};"
                 : "+f"(d[0]), "+f"(d[1]), "+f"(d[2]), "+f"(d[3])
                 : "r"(a[0]), "r"(a[1]), "r"(a[2]), "r"(a[3]), "r"(b0), "r"(b1));
}
__device__ __forceinline__ uint32_t pack_bf16(float a, float b) {
    __nv_bfloat162 t = __floats2bfloat162_rn(a, b);
    return *(uint32_t*)&t;
}

// ---------------- init (tiny now) ----------------
__global__ void init_kernel() {
    int g = blockIdx.x * blockDim.x + threadIdx.x;
    int stride = gridDim.x * blockDim.x;
    for (int i = g; i < NODES; i += stride) g_deg[i] = 0;
    if (g < RR) g_wsum[g] = 0.f;
}

// ---------------- weight prep ----------------
__global__ void prep1(const float* __restrict__ Wg, const float* __restrict__ attn_r,
                      const float* __restrict__ bt_src) {
    int r = blockIdx.x;
    int t = threadIdx.x;
    const float* wgr = Wg + (size_t)r * HID * HD;
    #pragma unroll
    for (int h = 0; h < HH; h++) {
        float s = 0.f;
        #pragma unroll
        for (int d = 0; d < DD; d++)
            s += wgr[t * HD + h * DD + d] * attn_r[(r * HH + h) * DD + d];
        g_gvec[(r * HID + t) * HH + h] = s;
    }
    float s = 0.f;
    for (int tt = 0; tt < HID; tt++) s += bt_src[r * HID + tt] * wgr[tt * HD + t];
    g_bc[r * HD + t] = s;
}

__global__ void prep2(const float* __restrict__ Wt_src, const float* __restrict__ Wg,
                      const float* __restrict__ Wt_dst, const float* __restrict__ bt_dst) {
    int k = blockIdx.x;
    int r = blockIdx.y;
    int j = threadIdx.x;
    if (k < HID) {
        __shared__ float arow[HID];
        arow[j] = Wt_src[((size_t)r * HID + k) * HID + j];
        __syncthreads();
        float s = 0.f;
        const float* wgr = Wg + (size_t)r * HID * HD;
        for (int t = 0; t < HID; t++) s += arow[t] * wgr[t * HD + j];
        g_Wc[((size_t)r * HID + k) * HD + j] = s;
    } else {
        int t = j;
        #pragma unroll
        for (int h = 0; h < HH; h++) {
            float s = 0.f;
            for (int tp = 0; tp < HID; tp++)
                s += Wt_dst[t * HID + tp] * g_gvec[(r * HID + tp) * HH + h];
            g_url[(r * HH + h) * HID + t] = s;
        }
        if (t < HH) {
            int h = t;
            float s = 0.f;
            for (int tp = 0; tp < HID; tp++)
                s += bt_dst[tp] * g_gvec[(r * HID + tp) * HH + h];
            g_erc[r * HH + h] = s;
        }
    }
}

__global__ void prep_b(const float* __restrict__ W1) {
    int idx = blockIdx.x * blockDim.x + threadIdx.x;
    if (idx >= 4 * 128 * 128) return;
    int mat = idx >> 14;
    int e = idx & 16383;
    int n = e >> 7;
    int k = e & 127;
    float w = (mat < 3) ? g_Wc[((size_t)mat * HID + k) * HD + n] : W1[k * 128 + n];
    __nv_bfloat16 hi = __float2bfloat16(w);
    __nv_bfloat16 lo = __float2bfloat16(w - __bfloat162float(hi));
    g_Bt[mat][0][n * BSTR + k] = hi;
    g_Bt[mat][1][n * BSTR + k] = lo;
}

// ---------------- mma.sync GEMM ----------------
#define A_HI_OFF 0
#define A_LO_OFF 34816
#define B_OFF    69632
#define GEMM_SMEM (69632 * 2)

template <int MODE>
__global__ __launch_bounds__(512, 1)
void gemm_mma(const float* __restrict__ Abase,
              const float* __restrict__ b1,
              const float* __restrict__ prebias,
              const float* __restrict__ W2,
              const float* __restrict__ attn_l,
              int M) {
    extern __shared__ __align__(16) char smem[];
    __shared__ float wrow[128];
    uint32_t sb = smem_to_u32(smem);
    int tid = threadIdx.x;
    int w = tid >> 5, lane = tid & 31;
    int r = blockIdx.y;
    int row0 = blockIdx.x * 128;

    const float* A = (MODE == 0) ? (Abase + (size_t)r * NN * HID)
                                 : (g_rst + (size_t)r * NN * HD);
    const float* pb = (MODE == 1) ? (prebias + r * HD) : nullptr;
    int mat = (MODE == 0) ? r : 3;

    {
        const uint4* src = (const uint4*)&g_Bt[mat][0][0];
        uint4* dst = (uint4*)(smem + B_OFF);
        for (int i = tid; i < 69632 / 16; i += 512) dst[i] = src[i];
    }
    for (int u = 0; u < 8; u++) {
        int g = u * 512 + tid;
        int row = g >> 5;
        int k0 = (g & 31) * 4;
        float f[4];
        if (row0 + row < M) {
            float4 v = *(const float4*)&A[(size_t)(row0 + row) * 128 + k0];
            f[0] = v.x; f[1] = v.y; f[2] = v.z; f[3] = v.w;
            if (MODE == 1) {
                float4 p = *(const float4*)&pb[k0];
                f[0] = elu(f[0] + p.x); f[1] = elu(f[1] + p.y);
                f[2] = elu(f[2] + p.z); f[3] = elu(f[3] + p.w);
            }
        } else {
            f[0] = f[1] = f[2] = f[3] = 0.f;
        }
        float fh[4], fl[4];
        #pragma unroll
        for (int j = 0; j < 4; j++) {
            __nv_bfloat16 h = __float2bfloat16(f[j]);
            fh[j] = __bfloat162float(h);
            fl[j] = f[j] - fh[j];
        }
        uint32_t off = (uint32_t)(row * BSTR + k0) * 2;
        *(uint2*)(smem + A_HI_OFF + off) = make_uint2(pack_bf16(fh[0], fh[1]), pack_bf16(fh[2], fh[3]));
        *(uint2*)(smem + A_LO_OFF + off) = make_uint2(pack_bf16(fl[0], fl[1]), pack_bf16(fl[2], fl[3]));
    }
    if (MODE == 1 && tid < 128) wrow[tid] = 0.f;
    __syncthreads();

    int m0 = (w & 7) * 16;
    int n0 = (w >> 3) * 64;

    uint32_t a_hi_addr = sb + A_HI_OFF + ((m0 + (lane & 15)) * BSTR + (lane >> 4) * 8) * 2;
    uint32_t a_lo_addr = a_hi_addr + (A_LO_OFF - A_HI_OFF);
    int b_n = n0 + (lane & 7) + ((lane >> 4) & 1) * 8;
    int b_k = ((lane >> 3) & 1) * 8;
    uint32_t b_hi_base = sb + B_OFF + (b_n * BSTR + b_k) * 2;
    uint32_t b_lo_base = b_hi_base + 34816;

    float acc[8][4];
    #pragma unroll
    for (int i = 0; i < 8; i++)
        #pragma unroll
        for (int j = 0; j < 4; j++) acc[i][j] = 0.f;

    #pragma unroll
    for (int ks = 0; ks < 8; ks++) {
        uint32_t kb = ks * 32;
        uint32_t ah[4], al_[4];
        ldsm4(ah, a_hi_addr + kb);
        ldsm4(al_, a_lo_addr + kb);
        #pragma unroll
        for (int g = 0; g < 4; g++) {
            uint32_t bh[4], bl[4];
            ldsm4(bh, b_hi_base + g * (16 * BSTR * 2) + kb);
            ldsm4(bl, b_lo_base + g * (16 * BSTR * 2) + kb);
            mma_bf16(acc[2 * g],     ah,  bh[0], bh[1]);
            mma_bf16(acc[2 * g + 1], ah,  bh[2], bh[3]);
            mma_bf16(acc[2 * g],     ah,  bl[0], bl[1]);
            mma_bf16(acc[2 * g + 1], ah,  bl[2], bl[3]);
            mma_bf16(acc[2 * g],     al_, bh[0], bh[1]);
            mma_bf16(acc[2 * g + 1], al_, bh[2], bh[3]);
        }
    }

    int rowA = row0 + m0 + (lane >> 2);
    int rowB = rowA + 8;

    if (MODE == 0) {
        float* C = g_hs + (size_t)r * NN * HD;
        float elA[2] = {0.f, 0.f}, elB[2] = {0.f, 0.f};
        #pragma unroll
        for (int f = 0; f < 8; f++) {
            int col = n0 + f * 8 + (lane & 3) * 2;
            int hl = f >> 2;
            int head = (n0 >> 5) + hl;
            float bc0 = g_bc[r * HD + col], bc1 = g_bc[r * HD + col + 1];
            float al0 = attn_l[(r * HH + head) * DD + (col - head * 32)];
            float al1 = attn_l[(r * HH + head) * DD + (col + 1 - head * 32)];
            float o00 = acc[f][0] + bc0, o01 = acc[f][1] + bc1;
            float o10 = acc[f][2] + bc0, o11 = acc[f][3] + bc1;
            elA[hl] += o00 * al0 + o01 * al1;
            elB[hl] += o10 * al0 + o11 * al1;
            if (rowA < M) *(float2*)&C[(size_t)rowA * 128 + col] = make_float2(o00, o01);
            if (rowB < M) *(float2*)&C[(size_t)rowB * 128 + col] = make_float2(o10, o11);
        }
        #pragma unroll
        for (int hl = 0; hl < 2; hl++) {
            float va = elA[hl], vb = elB[hl];
            va += __shfl_xor_sync(0xffffffffu, va, 1);
            va += __shfl_xor_sync(0xffffffffu, va, 2);
            vb += __shfl_xor_sync(0xffffffffu, vb, 1);
            vb += __shfl_xor_sync(0xffffffffu, vb, 2);
            if ((lane & 3) == 0) {
                int head = (n0 >> 5) + hl;
                if (rowA < M) g_el[((size_t)r * NN + rowA) * HH + head] = va;
                if (rowB < M) g_el[((size_t)r * NN + rowB) * HH + head] = vb;
            }
        }
    } else {
        float wpA = 0.f, wpB = 0.f;
        #pragma unroll
        for (int f = 0; f < 8; f++) {
            int col = n0 + f * 8 + (lane & 3) * 2;
            float b0 = b1[col], bb1 = b1[col + 1];
            float w0 = W2[col], w1 = W2[col + 1];
            wpA += tanhf(acc[f][0] + b0) * w0 + tanhf(acc[f][1] + bb1) * w1;
            wpB += tanhf(acc[f][2] + b0) * w0 + tanhf(acc[f][3] + bb1) * w1;
        }
        wpA += __shfl_xor_sync(0xffffffffu, wpA, 1);
        wpA += __shfl_xor_sync(0xffffffffu, wpA, 2);
        wpB += __shfl_xor_sync(0xffffffffu, wpB, 1);
        wpB += __shfl_xor_sync(0xffffffffu, wpB, 2);
        if ((lane & 3) == 0) {
            if (rowA < M) atomicAdd(&wrow[m0 + (lane >> 2)], wpA);
            if (rowB < M) atomicAdd(&wrow[m0 + (lane >> 2) + 8], wpB);
        }
        __syncthreads();
        if (tid < 128) {
            float v = wrow[tid];
            #pragma unroll
            for (int off = 16; off > 0; off >>= 1)
                v += __shfl_xor_sync(0xffffffffu, v, off);
            if ((tid & 31) == 0) atomicAdd(&g_wsum[r], v);
        }
    }
}

// ---------------- er ----------------
__global__ void er_kernel(const float* __restrict__ dst_feat) {
    __shared__ float s_url[RR * HH * HID];
    __shared__ float s_erc[RR * HH];
    int tid = threadIdx.x;
    for (int i = tid; i < RR * HH * HID; i += 256) s_url[i] = g_url[i];
    if (tid < RR * HH) s_erc[tid] = g_erc[tid];
    __syncthreads();

    int warp = tid >> 5, lane = tid & 31;
    int n = blockIdx.x * 8 + warp;
    if (n >= NN) return;

    float4 df = *(const float4*)&dst_feat[(size_t)n * HID + lane * 4];
    #pragma unroll
    for (int rh = 0; rh < RR * HH; rh++) {
        const float* u = &s_url[rh * HID + lane * 4];
        float p = df.x * u[0] + df.y * u[1] + df.z * u[2] + df.w * u[3];
        #pragma unroll
        for (int off = 16; off > 0; off >>= 1)
            p += __shfl_xor_sync(0xffffffffu, p, off);
        if (lane == 0) {
            int r = rh >> 2, h = rh & 3;
            g_er[((size_t)r * NN + n) * HH + h] = p + s_erc[rh];
        }
    }
}

// ---------------- CSR build ----------------
__global__ void count_deg(const int* __restrict__ di) {
    int idx = blockIdx.x * blockDim.x + threadIdx.x;
    if (idx >= NEDGE) return;
    int r = idx / EE;
    atomicAdd(&g_deg[r * NN + di[idx]], 1);
}

__global__ void scan1() {
    __shared__ int warp_off[8];
    int b = blockIdx.x, t = threadIdx.x;
    int lane = t & 31, w = t >> 5;
    int base = b * SCAN_BLK + t * 8;
    int v[8];
    int tsum = 0;
    #pragma unroll
    for (int j = 0; j < 8; j++) {
        int x = (base + j < NODES) ? g_deg[base + j] : 0;
        v[j] = tsum;
        tsum += x;
    }
    int inc = tsum;
    #pragma unroll
    for (int off = 1; off < 32; off <<= 1) {
        int y = __shfl_up_sync(0xffffffffu, inc, off);
        if (lane >= off) inc += y;
    }
    if (lane == 31) warp_off[w] = inc;
    __syncthreads();
    if (t == 0) {
        int s = 0;
        #pragma unroll
        for (int i = 0; i < 8; i++) { int x = warp_off[i]; warp_off[i] = s; s += x; }
        g_bsum[b] = s;
    }
    __syncthreads();
    int texcl = warp_off[w] + inc - tsum;
    #pragma unroll
    for (int j = 0; j < 8; j++)
        if (base + j < NODES) g_ptr[base + j] = texcl + v[j];
}

__global__ void scan2() {
    __shared__ int s[256];
    int t = threadIdx.x;
    s[t] = (t < NSCAN) ? g_bsum[t] : 0;
    __syncthreads();
    for (int off = 1; off < 256; off <<= 1) {
        int v = (t >= off) ? s[t - off] : 0;
        __syncthreads();
        s[t] += v;
        __syncthreads();
    }
    if (t < NSCAN) g_bsum[t] = (t == 0) ? 0 : s[t - 1];
}

__global__ void scan3() {
    int i = blockIdx.x * blockDim.x + threadIdx.x;
    if (i < NODES) g_ptr[i] += g_bsum[i / SCAN_BLK];
}

__global__ void scatter_edges(const int* __restrict__ si, const int* __restrict__ di) {
    int idx = blockIdx.x * blockDim.x + threadIdx.x;
    if (idx >= NEDGE) return;
    int r = idx / EE;
    int pos = atomicAdd(&g_ptr[r * NN + di[idx]], 1);
    g_esrc[pos] = si[idx];
}

// ---------------- fused softmax + aggregation: one warp per (r, dst) ----------------
__global__ __launch_bounds__(256)
void agg_kernel() {
    int warp = threadIdx.x >> 5, lane = threadIdx.x & 31;
    int nodeid = blockIdx.x * 8 + warp;
    if (nodeid >= NODES) return;
    int r = nodeid / NN;
    int end = g_ptr[nodeid];            // after scatter, ptr = end of bucket
    int deg = g_deg[nodeid];
    int start = end - deg;

    float4 er4 = *(const float4*)&g_er[(size_t)nodeid * HH];
    const float* elbase = g_el + (size_t)r * NN * HH;
    const float* hsbase = g_hs + (size_t)r * NN * HD;

    float4 ssum = make_float4(0.f, 0.f, 0.f, 0.f);
    for (int i = start; i < end; i++) {
        int s = __ldg(&g_esrc[i]);
        float4 el4 = *(const float4*)&elbase[(size_t)s * HH];
        ssum.x += __expf(lrelu(el4.x + er4.x));
        ssum.y += __expf(lrelu(el4.y + er4.y));
        ssum.z += __expf(lrelu(el4.z + er4.z));
        ssum.w += __expf(lrelu(el4.w + er4.w));
    }
    float4 rcp = make_float4(1.f / (ssum.x + 1e-9f), 1.f / (ssum.y + 1e-9f),
                             1.f / (ssum.z + 1e-9f), 1.f / (ssum.w + 1e-9f));
    int h = lane >> 3;
    float rc = (h == 0) ? rcp.x : (h == 1) ? rcp.y : (h == 2) ? rcp.z : rcp.w;

    float4 acc = make_float4(0.f, 0.f, 0.f, 0.f);
    for (int i = start; i < end; i++) {
        int s = __ldg(&g_esrc[i]);
        float4 el4 = *(const float4*)&elbase[(size_t)s * HH];
        float e = (h == 0) ? el4.x + er4.x : (h == 1) ? el4.y + er4.y
                : (h == 2) ? el4.z + er4.z : el4.w + er4.w;
        float alpha = __expf(lrelu(e)) * rc;
        float4 hv = *(const float4*)&hsbase[(size_t)s * HD + lane * 4];
        acc.x += alpha * hv.x; acc.y += alpha * hv.y;
        acc.z += alpha * hv.z; acc.w += alpha * hv.w;
    }
    *(float4*)&g_rst[(size_t)nodeid * HD + lane * 4] = acc;
}

// ---------------- semantic softmax + output ----------------
__global__ void finalize_a(float* att_out) {
    if (threadIdx.x == 0) {
        float w[RR];
        float mx = -1e30f;
        for (int r = 0; r < RR; r++) { w[r] = g_wsum[r] / (float)NN; mx = fmaxf(mx, w[r]); }
        float s = 0.f;
        for (int r = 0; r < RR; r++) { w[r] = expf(w[r] - mx); s += w[r]; }
        for (int r = 0; r < RR; r++) {
            float a = w[r] / s;
            g_a[r] = a;
            if (att_out) att_out[r] = a;
        }
    }
}

__global__ void out_z_kernel(const float* __restrict__ bias_g, float* __restrict__ out) {
    int i = blockIdx.x * blockDim.x + threadIdx.x;
    if (i >= NN * HD) return;
    int j = i & 127;
    float s = 0.f;
    #pragma unroll
    for (int r = 0; r < RR; r++) {
        float v = g_rst[(size_t)r * NN * HD + i] + bias_g[r * HD + j];
        v = v > 0.f ? v : expm1f(v);
        s += g_a[r] * v;
    }
    out[i] = s;
}

// ---------------- launch ----------------
extern "C" void kernel_launch(void* const* d_in, const int* in_sizes, int n_in,
                              void* d_out, int out_size) {
    const float* dst_feat  = (const float*)d_in[0];
    const float* src_feats = (const float*)d_in[1];
    const int*   src_idx   = (const int*)d_in[2];
    const int*   dst_idx   = (const int*)d_in[3];
    const float* Wt_dst    = (const float*)d_in[4];
    const float* bt_dst    = (const float*)d_in[5];
    const float* Wt_src    = (const float*)d_in[6];
    const float* bt_src    = (const float*)d_in[7];
    const float* Wg        = (const float*)d_in[8];
    const float* attn_l    = (const float*)d_in[9];
    const float* attn_r    = (const float*)d_in[10];
    const float* bias_g    = (const float*)d_in[11];
    const float* W1        = (const float*)d_in[12];
    const float* b1        = (const float*)d_in[13];
    const float* W2        = (const float*)d_in[14];
    float* out = (float*)d_out;
    float* att_out = (out_size >= NN * HD + RR) ? out + (size_t)NN * HD : nullptr;

    cudaFuncSetAttribute(gemm_mma<0>, cudaFuncAttributeMaxDynamicSharedMemorySize, GEMM_SMEM);
    cudaFuncSetAttribute(gemm_mma<1>, cudaFuncAttributeMaxDynamicSharedMemorySize, GEMM_SMEM);

    init_kernel<<<(NODES + 255) / 256, 256>>>();
    prep1<<<RR, 128>>>(Wg, attn_r, bt_src);
    prep2<<<dim3(HID + 1, RR), 128>>>(Wt_src, Wg, Wt_dst, bt_dst);
    prep_b<<<(4 * 128 * 128 + 255) / 256, 256>>>(W1);

    // CSR build (independent of GEMM results)
    count_deg<<<(NEDGE + 255) / 256, 256>>>(dst_idx);
    scan1<<<NSCAN, 256>>>();
    scan2<<<1, 256>>>();
    scan3<<<(NODES + 255) / 256, 256>>>();
    scatter_edges<<<(NEDGE + 255) / 256, 256>>>(src_idx, dst_idx);

    int tiles = (NN + 127) / 128;

    gemm_mma<0><<<dim3(tiles, RR), 512, GEMM_SMEM>>>(
        src_feats, nullptr, nullptr, nullptr, attn_l, NN);

    er_kernel<<<(NN + 7) / 8, 256>>>(dst_feat);

    agg_kernel<<<(NODES + 7) / 8, 256>>>();

    gemm_mma<1><<<dim3(tiles, RR), 512, GEMM_SMEM>>>(
        nullptr, b1, bias_g, W2, nullptr, NN);

    finalize_a<<<1, 32>>>(att_out);
    out_z_kernel<<<(NN * HD + 255) / 256, 256>>>(bias_g, out);
}

// round 7
// speedup vs baseline: 1.6190x; 1.0584x over previous
#include <cuda_runtime.h>
#include <cuda_bf16.h>
#include <math.h>
#include <stdint.h>

#define NN 100000
#define RR 3
#define EE 320000
#define HH 4
#define DD 32
#define HD 128   // H*D
#define HID 128
#define NODES (RR * NN)
#define NEDGE (RR * EE)
#define SCAN_BLK 2048
#define NSCAN ((NODES + SCAN_BLK - 1) / SCAN_BLK)   // 147

// ---------------- device scratch (no allocs allowed) ----------------
__device__ __align__(16) float g_hs  [RR * NN * HD];
__device__ __align__(16) float g_rst [RR * NN * HD];
__device__ __align__(16) float g_el  [RR * NN * HH];
__device__ __align__(16) float g_er  [RR * NN * HH];
__device__ __align__(16) float g_Wc  [RR * HID * HD];
__device__ __align__(16) float g_bc  [RR * HD];
__device__ __align__(16) float g_gvec[RR * HID * HH];
__device__ __align__(16) float g_url [RR * HH * HID];
__device__ __align__(16) float g_erc [RR * HH];
__device__ float g_wsum[RR];
__device__ float g_a[RR];

// CSR scratch
__device__ int g_deg [NODES];
__device__ int g_ptr [NODES];
__device__ int g_bsum[NSCAN + 1];
__device__ int g_esrc[NEDGE];

// Prebuilt bf16 B tiles (stored [n][k]), padded stride 136.
#define BSTR 136
__device__ __align__(16) __nv_bfloat16 g_Bt[4][2][128 * BSTR];

// ---------------- helpers ----------------
__device__ __forceinline__ float lrelu(float x) { return x > 0.f ? x : 0.2f * x; }
__device__ __forceinline__ float elu(float x)   { return x > 0.f ? x : expm1f(x); }

__device__ __forceinline__ uint32_t smem_to_u32(const void* p) {
    uint32_t a;
    asm("{ .reg .u64 t; cvta.to.shared.u64 t, %1; cvt.u32.u64 %0, t; }" : "=r"(a) : "l"(p));
    return a;
}
__device__ __forceinline__ void ldsm4(uint32_t* r, uint32_t addr) {
    asm volatile("ldmatrix.sync.aligned.m8n8.x4.shared.b16 {%0,%1,%2,%3}, [%4];"
                 : "=r"(r[0]), "=r"(r[1]), "=r"(r[2]), "=r"(r[3]) : "r"(addr));
}
__device__ __forceinline__ void mma_bf16(float* d, const uint32_t* a,
                                         uint32_t b0, uint32_t b1) {
    asm volatile("mma.sync.aligned.m16n8k16.row.col.f32.bf16.bf16.f32 "
                 "{%0,%1,%2,%3}, {%4,%5,%6,%7}, {%8,%9}, {%0,%1,%2,%3};"
                 : "+f"(d[0]), "+f"(d[1]), "+f"(d[2]), "+f"(d[3])
                 : "r"(a[0]), "r"(a[1]), "r"(a[2]), "r"(a[3]), "r"(b0), "r"(b1));
}
__device__ __forceinline__ uint32_t pack_bf16(float a, float b) {
    __nv_bfloat162 t = __floats2bfloat162_rn(a, b);
    return *(uint32_t*)&t;
}

// ---------------- init ----------------
__global__ void init_kernel() {
    int g = blockIdx.x * blockDim.x + threadIdx.x;
    int stride = gridDim.x * blockDim.x;
    for (int i = g; i < NODES; i += stride) g_deg[i] = 0;
    if (g < RR) g_wsum[g] = 0.f;
}

// ---------------- weight prep ----------------
__global__ void prep1(const float* __restrict__ Wg, const float* __restrict__ attn_r,
                      const float* __restrict__ bt_src) {
    int r = blockIdx.x;
    int t = threadIdx.x;
    const float* wgr = Wg + (size_t)r * HID * HD;
    #pragma unroll
    for (int h = 0; h < HH; h++) {
        float s = 0.f;
        #pragma unroll
        for (int d = 0; d < DD; d++)
            s += wgr[t * HD + h * DD + d] * attn_r[(r * HH + h) * DD + d];
        g_gvec[(r * HID + t) * HH + h] = s;
    }
    float s = 0.f;
    for (int tt = 0; tt < HID; tt++) s += bt_src[r * HID + tt] * wgr[tt * HD + t];
    g_bc[r * HD + t] = s;
}

__global__ void prep2(const float* __restrict__ Wt_src, const float* __restrict__ Wg,
                      const float* __restrict__ Wt_dst, const float* __restrict__ bt_dst) {
    int k = blockIdx.x;
    int r = blockIdx.y;
    int j = threadIdx.x;
    if (k < HID) {
        __shared__ float arow[HID];
        arow[j] = Wt_src[((size_t)r * HID + k) * HID + j];
        __syncthreads();
        float s = 0.f;
        const float* wgr = Wg + (size_t)r * HID * HD;
        for (int t = 0; t < HID; t++) s += arow[t] * wgr[t * HD + j];
        g_Wc[((size_t)r * HID + k) * HD + j] = s;
    } else {
        int t = j;
        #pragma unroll
        for (int h = 0; h < HH; h++) {
            float s = 0.f;
            for (int tp = 0; tp < HID; tp++)
                s += Wt_dst[t * HID + tp] * g_gvec[(r * HID + tp) * HH + h];
            g_url[(r * HH + h) * HID + t] = s;
        }
        if (t < HH) {
            int h = t;
            float s = 0.f;
            for (int tp = 0; tp < HID; tp++)
                s += bt_dst[tp] * g_gvec[(r * HID + tp) * HH + h];
            g_erc[r * HH + h] = s;
        }
    }
}

__global__ void prep_b(const float* __restrict__ W1) {
    int idx = blockIdx.x * blockDim.x + threadIdx.x;
    if (idx >= 4 * 128 * 128) return;
    int mat = idx >> 14;
    int e = idx & 16383;
    int n = e >> 7;
    int k = e & 127;
    float w = (mat < 3) ? g_Wc[((size_t)mat * HID + k) * HD + n] : W1[k * 128 + n];
    __nv_bfloat16 hi = __float2bfloat16(w);
    __nv_bfloat16 lo = __float2bfloat16(w - __bfloat162float(hi));
    g_Bt[mat][0][n * BSTR + k] = hi;
    g_Bt[mat][1][n * BSTR + k] = lo;
}

// ---------------- mma.sync GEMM ----------------
#define A_HI_OFF 0
#define A_LO_OFF 34816
#define B_OFF    69632
#define GEMM_SMEM (69632 * 2)

template <int MODE>
__global__ __launch_bounds__(512, 1)
void gemm_mma(const float* __restrict__ Abase,
              const float* __restrict__ b1,
              const float* __restrict__ prebias,
              const float* __restrict__ W2,
              const float* __restrict__ attn_l,
              int M) {
    extern __shared__ __align__(16) char smem[];
    __shared__ float wrow[128];
    uint32_t sb = smem_to_u32(smem);
    int tid = threadIdx.x;
    int w = tid >> 5, lane = tid & 31;
    int r = blockIdx.y;
    int row0 = blockIdx.x * 128;

    const float* A = (MODE == 0) ? (Abase + (size_t)r * NN * HID)
                                 : (g_rst + (size_t)r * NN * HD);
    const float* pb = (MODE == 1) ? (prebias + r * HD) : nullptr;
    int mat = (MODE == 0) ? r : 3;

    {
        const uint4* src = (const uint4*)&g_Bt[mat][0][0];
        uint4* dst = (uint4*)(smem + B_OFF);
        for (int i = tid; i < 69632 / 16; i += 512) dst[i] = src[i];
    }
    for (int u = 0; u < 8; u++) {
        int g = u * 512 + tid;
        int row = g >> 5;
        int k0 = (g & 31) * 4;
        float f[4];
        if (row0 + row < M) {
            float4 v = *(const float4*)&A[(size_t)(row0 + row) * 128 + k0];
            f[0] = v.x; f[1] = v.y; f[2] = v.z; f[3] = v.w;
            if (MODE == 1) {
                float4 p = *(const float4*)&pb[k0];
                f[0] = elu(f[0] + p.x); f[1] = elu(f[1] + p.y);
                f[2] = elu(f[2] + p.z); f[3] = elu(f[3] + p.w);
            }
        } else {
            f[0] = f[1] = f[2] = f[3] = 0.f;
        }
        float fh[4], fl[4];
        #pragma unroll
        for (int j = 0; j < 4; j++) {
            __nv_bfloat16 h = __float2bfloat16(f[j]);
            fh[j] = __bfloat162float(h);
            fl[j] = f[j] - fh[j];
        }
        uint32_t off = (uint32_t)(row * BSTR + k0) * 2;
        *(uint2*)(smem + A_HI_OFF + off) = make_uint2(pack_bf16(fh[0], fh[1]), pack_bf16(fh[2], fh[3]));
        *(uint2*)(smem + A_LO_OFF + off) = make_uint2(pack_bf16(fl[0], fl[1]), pack_bf16(fl[2], fl[3]));
    }
    if (MODE == 1 && tid < 128) wrow[tid] = 0.f;
    __syncthreads();

    int m0 = (w & 7) * 16;
    int n0 = (w >> 3) * 64;

    uint32_t a_hi_addr = sb + A_HI_OFF + ((m0 + (lane & 15)) * BSTR + (lane >> 4) * 8) * 2;
    uint32_t a_lo_addr = a_hi_addr + (A_LO_OFF - A_HI_OFF);
    int b_n = n0 + (lane & 7) + ((lane >> 4) & 1) * 8;
    int b_k = ((lane >> 3) & 1) * 8;
    uint32_t b_hi_base = sb + B_OFF + (b_n * BSTR + b_k) * 2;
    uint32_t b_lo_base = b_hi_base + 34816;

    float acc[8][4];
    #pragma unroll
    for (int i = 0; i < 8; i++)
        #pragma unroll
        for (int j = 0; j < 4; j++) acc[i][j] = 0.f;

    #pragma unroll
    for (int ks = 0; ks < 8; ks++) {
        uint32_t kb = ks * 32;
        uint32_t ah[4], al_[4];
        ldsm4(ah, a_hi_addr + kb);
        ldsm4(al_, a_lo_addr + kb);
        #pragma unroll
        for (int g = 0; g < 4; g++) {
            uint32_t bh[4], bl[4];
            ldsm4(bh, b_hi_base + g * (16 * BSTR * 2) + kb);
            ldsm4(bl, b_lo_base + g * (16 * BSTR * 2) + kb);
            mma_bf16(acc[2 * g],     ah,  bh[0], bh[1]);
            mma_bf16(acc[2 * g + 1], ah,  bh[2], bh[3]);
            mma_bf16(acc[2 * g],     ah,  bl[0], bl[1]);
            mma_bf16(acc[2 * g + 1], ah,  bl[2], bl[3]);
            mma_bf16(acc[2 * g],     al_, bh[0], bh[1]);
            mma_bf16(acc[2 * g + 1], al_, bh[2], bh[3]);
        }
    }

    int rowA = row0 + m0 + (lane >> 2);
    int rowB = rowA + 8;

    if (MODE == 0) {
        float* C = g_hs + (size_t)r * NN * HD;
        float elA[2] = {0.f, 0.f}, elB[2] = {0.f, 0.f};
        #pragma unroll
        for (int f = 0; f < 8; f++) {
            int col = n0 + f * 8 + (lane & 3) * 2;
            int hl = f >> 2;
            int head = (n0 >> 5) + hl;
            float bc0 = g_bc[r * HD + col], bc1 = g_bc[r * HD + col + 1];
            float al0 = attn_l[(r * HH + head) * DD + (col - head * 32)];
            float al1 = attn_l[(r * HH + head) * DD + (col + 1 - head * 32)];
            float o00 = acc[f][0] + bc0, o01 = acc[f][1] + bc1;
            float o10 = acc[f][2] + bc0, o11 = acc[f][3] + bc1;
            elA[hl] += o00 * al0 + o01 * al1;
            elB[hl] += o10 * al0 + o11 * al1;
            if (rowA < M) *(float2*)&C[(size_t)rowA * 128 + col] = make_float2(o00, o01);
            if (rowB < M) *(float2*)&C[(size_t)rowB * 128 + col] = make_float2(o10, o11);
        }
        #pragma unroll
        for (int hl = 0; hl < 2; hl++) {
            float va = elA[hl], vb = elB[hl];
            va += __shfl_xor_sync(0xffffffffu, va, 1);
            va += __shfl_xor_sync(0xffffffffu, va, 2);
            vb += __shfl_xor_sync(0xffffffffu, vb, 1);
            vb += __shfl_xor_sync(0xffffffffu, vb, 2);
            if ((lane & 3) == 0) {
                int head = (n0 >> 5) + hl;
                if (rowA < M) g_el[((size_t)r * NN + rowA) * HH + head] = va;
                if (rowB < M) g_el[((size_t)r * NN + rowB) * HH + head] = vb;
            }
        }
    } else {
        float wpA = 0.f, wpB = 0.f;
        #pragma unroll
        for (int f = 0; f < 8; f++) {
            int col = n0 + f * 8 + (lane & 3) * 2;
            float b0 = b1[col], bb1 = b1[col + 1];
            float w0 = W2[col], w1 = W2[col + 1];
            wpA += tanhf(acc[f][0] + b0) * w0 + tanhf(acc[f][1] + bb1) * w1;
            wpB += tanhf(acc[f][2] + b0) * w0 + tanhf(acc[f][3] + bb1) * w1;
        }
        wpA += __shfl_xor_sync(0xffffffffu, wpA, 1);
        wpA += __shfl_xor_sync(0xffffffffu, wpA, 2);
        wpB += __shfl_xor_sync(0xffffffffu, wpB, 1);
        wpB += __shfl_xor_sync(0xffffffffu, wpB, 2);
        if ((lane & 3) == 0) {
            if (rowA < M) atomicAdd(&wrow[m0 + (lane >> 2)], wpA);
            if (rowB < M) atomicAdd(&wrow[m0 + (lane >> 2) + 8], wpB);
        }
        __syncthreads();
        if (tid < 128) {
            float v = wrow[tid];
            #pragma unroll
            for (int off = 16; off > 0; off >>= 1)
                v += __shfl_xor_sync(0xffffffffu, v, off);
            if ((tid & 31) == 0) atomicAdd(&g_wsum[r], v);
        }
    }
}

// ---------------- er ----------------
__global__ void er_kernel(const float* __restrict__ dst_feat) {
    __shared__ float s_url[RR * HH * HID];
    __shared__ float s_erc[RR * HH];
    int tid = threadIdx.x;
    for (int i = tid; i < RR * HH * HID; i += 256) s_url[i] = g_url[i];
    if (tid < RR * HH) s_erc[tid] = g_erc[tid];
    __syncthreads();

    int warp = tid >> 5, lane = tid & 31;
    int n = blockIdx.x * 8 + warp;
    if (n >= NN) return;

    float4 df = *(const float4*)&dst_feat[(size_t)n * HID + lane * 4];
    #pragma unroll
    for (int rh = 0; rh < RR * HH; rh++) {
        const float* u = &s_url[rh * HID + lane * 4];
        float p = df.x * u[0] + df.y * u[1] + df.z * u[2] + df.w * u[3];
        #pragma unroll
        for (int off = 16; off > 0; off >>= 1)
            p += __shfl_xor_sync(0xffffffffu, p, off);
        if (lane == 0) {
            int r = rh >> 2, h = rh & 3;
            g_er[((size_t)r * NN + n) * HH + h] = p + s_erc[rh];
        }
    }
}

// ---------------- CSR build ----------------
__global__ void count_deg(const int* __restrict__ di) {
    int idx = blockIdx.x * blockDim.x + threadIdx.x;
    if (idx >= NEDGE) return;
    int r = idx / EE;
    atomicAdd(&g_deg[r * NN + di[idx]], 1);
}

__global__ void scan1() {
    __shared__ int warp_off[8];
    int b = blockIdx.x, t = threadIdx.x;
    int lane = t & 31, w = t >> 5;
    int base = b * SCAN_BLK + t * 8;
    int v[8];
    int tsum = 0;
    #pragma unroll
    for (int j = 0; j < 8; j++) {
        int x = (base + j < NODES) ? g_deg[base + j] : 0;
        v[j] = tsum;
        tsum += x;
    }
    int inc = tsum;
    #pragma unroll
    for (int off = 1; off < 32; off <<= 1) {
        int y = __shfl_up_sync(0xffffffffu, inc, off);
        if (lane >= off) inc += y;
    }
    if (lane == 31) warp_off[w] = inc;
    __syncthreads();
    if (t == 0) {
        int s = 0;
        #pragma unroll
        for (int i = 0; i < 8; i++) { int x = warp_off[i]; warp_off[i] = s; s += x; }
        g_bsum[b] = s;
    }
    __syncthreads();
    int texcl = warp_off[w] + inc - tsum;
    #pragma unroll
    for (int j = 0; j < 8; j++)
        if (base + j < NODES) g_ptr[base + j] = texcl + v[j];
}

__global__ void scan2() {
    __shared__ int s[256];
    int t = threadIdx.x;
    s[t] = (t < NSCAN) ? g_bsum[t] : 0;
    __syncthreads();
    for (int off = 1; off < 256; off <<= 1) {
        int v = (t >= off) ? s[t - off] : 0;
        __syncthreads();
        s[t] += v;
        __syncthreads();
    }
    if (t < NSCAN) g_bsum[t] = (t == 0) ? 0 : s[t - 1];
}

__global__ void scan3() {
    int i = blockIdx.x * blockDim.x + threadIdx.x;
    if (i < NODES) g_ptr[i] += g_bsum[i / SCAN_BLK];
}

__global__ void scatter_edges(const int* __restrict__ si, const int* __restrict__ di) {
    int idx = blockIdx.x * blockDim.x + threadIdx.x;
    if (idx >= NEDGE) return;
    int r = idx / EE;
    int pos = atomicAdd(&g_ptr[r * NN + di[idx]], 1);
    g_esrc[pos] = si[idx];
}

// ---------------- fused softmax + aggregation: ONE pass, one warp per (r, dst) ------
// Softmax normalization factored out: acc = sum(ex*hs); rst = acc / (sum(ex)+eps)
__global__ __launch_bounds__(512)
void agg_kernel() {
    int warp = threadIdx.x >> 5, lane = threadIdx.x & 31;
    int nodeid = blockIdx.x * 16 + warp;
    if (nodeid >= NODES) return;
    int r = nodeid / NN;
    int end = g_ptr[nodeid];                         // after scatter, ptr = end
    int start = (nodeid == 0) ? 0 : g_ptr[nodeid - 1];
    int h = lane >> 3;

    float er = g_er[(size_t)nodeid * HH + h];
    const float* elbase = g_el + (size_t)r * NN * HH;
    const float* hsbase = g_hs + (size_t)r * NN * HD;

    float ssum = 0.f;
    float4 acc = make_float4(0.f, 0.f, 0.f, 0.f);

    int i = start;
    for (; i + 2 <= end; i += 2) {
        int s0 = __ldg(&g_esrc[i]);
        int s1 = __ldg(&g_esrc[i + 1]);
        float e0 = __ldg(&elbase[(size_t)s0 * HH + h]) + er;
        float e1 = __ldg(&elbase[(size_t)s1 * HH + h]) + er;
        float4 hv0 = *(const float4*)&hsbase[(size_t)s0 * HD + lane * 4];
        float4 hv1 = *(const float4*)&hsbase[(size_t)s1 * HD + lane * 4];
        float x0 = __expf(lrelu(e0));
        float x1 = __expf(lrelu(e1));
        ssum += x0 + x1;
        acc.x += x0 * hv0.x + x1 * hv1.x;
        acc.y += x0 * hv0.y + x1 * hv1.y;
        acc.z += x0 * hv0.z + x1 * hv1.z;
        acc.w += x0 * hv0.w + x1 * hv1.w;
    }
    if (i < end) {
        int s0 = __ldg(&g_esrc[i]);
        float e0 = __ldg(&elbase[(size_t)s0 * HH + h]) + er;
        float x0 = __expf(lrelu(e0));
        float4 hv0 = *(const float4*)&hsbase[(size_t)s0 * HD + lane * 4];
        ssum += x0;
        acc.x += x0 * hv0.x; acc.y += x0 * hv0.y;
        acc.z += x0 * hv0.z; acc.w += x0 * hv0.w;
    }

    float rc = 1.f / (ssum + 1e-9f);
    acc.x *= rc; acc.y *= rc; acc.z *= rc; acc.w *= rc;
    *(float4*)&g_rst[(size_t)nodeid * HD + lane * 4] = acc;
}

// ---------------- semantic softmax + output ----------------
__global__ void finalize_a(float* att_out) {
    if (threadIdx.x == 0) {
        float w[RR];
        float mx = -1e30f;
        for (int r = 0; r < RR; r++) { w[r] = g_wsum[r] / (float)NN; mx = fmaxf(mx, w[r]); }
        float s = 0.f;
        for (int r = 0; r < RR; r++) { w[r] = expf(w[r] - mx); s += w[r]; }
        for (int r = 0; r < RR; r++) {
            float a = w[r] / s;
            g_a[r] = a;
            if (att_out) att_out[r] = a;
        }
    }
}

__global__ void out_z_kernel(const float* __restrict__ bias_g, float* __restrict__ out) {
    int i = blockIdx.x * blockDim.x + threadIdx.x;
    if (i >= NN * HD) return;
    int j = i & 127;
    float s = 0.f;
    #pragma unroll
    for (int r = 0; r < RR; r++) {
        float v = g_rst[(size_t)r * NN * HD + i] + bias_g[r * HD + j];
        v = v > 0.f ? v : expm1f(v);
        s += g_a[r] * v;
    }
    out[i] = s;
}

// ---------------- launch ----------------
extern "C" void kernel_launch(void* const* d_in, const int* in_sizes, int n_in,
                              void* d_out, int out_size) {
    const float* dst_feat  = (const float*)d_in[0];
    const float* src_feats = (const float*)d_in[1];
    const int*   src_idx   = (const int*)d_in[2];
    const int*   dst_idx   = (const int*)d_in[3];
    const float* Wt_dst    = (const float*)d_in[4];
    const float* bt_dst    = (const float*)d_in[5];
    const float* Wt_src    = (const float*)d_in[6];
    const float* bt_src    = (const float*)d_in[7];
    const float* Wg        = (const float*)d_in[8];
    const float* attn_l    = (const float*)d_in[9];
    const float* attn_r    = (const float*)d_in[10];
    const float* bias_g    = (const float*)d_in[11];
    const float* W1        = (const float*)d_in[12];
    const float* b1        = (const float*)d_in[13];
    const float* W2        = (const float*)d_in[14];
    float* out = (float*)d_out;
    float* att_out = (out_size >= NN * HD + RR) ? out + (size_t)NN * HD : nullptr;

    cudaFuncSetAttribute(gemm_mma<0>, cudaFuncAttributeMaxDynamicSharedMemorySize, GEMM_SMEM);
    cudaFuncSetAttribute(gemm_mma<1>, cudaFuncAttributeMaxDynamicSharedMemorySize, GEMM_SMEM);

    init_kernel<<<(NODES + 255) / 256, 256>>>();
    prep1<<<RR, 128>>>(Wg, attn_r, bt_src);
    prep2<<<dim3(HID + 1, RR), 128>>>(Wt_src, Wg, Wt_dst, bt_dst);
    prep_b<<<(4 * 128 * 128 + 255) / 256, 256>>>(W1);

    // CSR build (independent of GEMM results)
    count_deg<<<(NEDGE + 255) / 256, 256>>>(dst_idx);
    scan1<<<NSCAN, 256>>>();
    scan2<<<1, 256>>>();
    scan3<<<(NODES + 255) / 256, 256>>>();
    scatter_edges<<<(NEDGE + 255) / 256, 256>>>(src_idx, dst_idx);

    int tiles = (NN + 127) / 128;

    gemm_mma<0><<<dim3(tiles, RR), 512, GEMM_SMEM>>>(
        src_feats, nullptr, nullptr, nullptr, attn_l, NN);

    er_kernel<<<(NN + 7) / 8, 256>>>(dst_feat);

    agg_kernel<<<(NODES + 15) / 16, 512>>>();

    gemm_mma<1><<<dim3(tiles, RR), 512, GEMM_SMEM>>>(
        nullptr, b1, bias_g, W2, nullptr, NN);

    finalize_a<<<1, 32>>>(att_out);
    out_z_kernel<<<(NN * HD + 255) / 256, 256>>>(bias_g, out);
}